// round 1
// baseline (speedup 1.0000x reference)
#include <cuda_runtime.h>
#include <math.h>

// Problem constants
#define BB 128
#define TT 512
#define EE 256
#define HH 1024
#define G4H 4096
#define KL0 1280   // E + H
#define KL1 2048   // 2H
#define NCTA 128
#define NTHR 256
#define KT 32

// -------- persistent device state --------
__device__ float g_h0[2][BB * HH];
__device__ float g_h1[2][BB * HH];
__device__ float g_c0[BB * HH];
__device__ float g_c1[BB * HH];

// grid barrier (self-resetting: count returns to 0 after each barrier,
// gen compared relative to a base read at kernel start -> replay-safe)
__device__ unsigned g_barcnt;
__device__ unsigned g_bargen;

__device__ __forceinline__ void grid_sync(unsigned base, unsigned nbar) {
    __syncthreads();
    if (threadIdx.x == 0) {
        __threadfence();
        unsigned old = atomicAdd(&g_barcnt, 1u);
        if (old == gridDim.x - 1) {
            g_barcnt = 0;
            __threadfence();
            atomicAdd(&g_bargen, 1u);
        } else {
            while ((*(volatile unsigned*)&g_bargen) - base < nbar) {
                __nanosleep(64);
            }
            __threadfence();
        }
    }
    __syncthreads();
}

__device__ __forceinline__ float sigf(float x) {
    return 1.0f / (1.0f + expf(-x));
}

__global__ void __launch_bounds__(NTHR, 1)
lstm_encoder_kernel(const int* __restrict__ input_batch,
                    const int* __restrict__ input_lengths,
                    const float* __restrict__ emb,
                    const float* __restrict__ W0,
                    const float* __restrict__ b0,
                    const float* __restrict__ W1,
                    const float* __restrict__ b1,
                    float* __restrict__ out) {
    __shared__ float As[KT][132];     // k-major A tile, padded
    __shared__ float Bs[KT][32];      // k-major B tile
    __shared__ float Zs[BB][36];      // gate pre-activations for this CTA's 32 cols
    __shared__ int   sidx[BB];
    __shared__ int   slen[BB];
    __shared__ float sb0[32], sb1[32];

    const int tid   = threadIdx.x;
    const int cta   = blockIdx.x;
    const int cbase = cta * 8;        // this CTA owns h columns [cbase, cbase+8)
    const int tm    = tid & 31;       // 32 m-tiles of 4 rows
    const int tn    = tid >> 5;       // 8 n-tiles of 4 cols

    unsigned base = *(volatile unsigned*)&g_bargen;
    unsigned nbar = 0;

    // ---- init state buffers (parity-0 buffers + cell states) ----
    for (int i = cta * NTHR + tid; i < BB * HH; i += NCTA * NTHR) {
        g_h0[0][i] = 0.0f;
        g_h1[0][i] = 0.0f;
        g_c0[i] = 0.0f;
        g_c1[i] = 0.0f;
    }
    if (tid < BB) slen[tid] = input_lengths[tid];
    if (tid < 32) {
        int col = (tid >> 3) * HH + cbase + (tid & 7);
        sb0[tid] = b0[col];
        sb1[tid] = b1[col];
    }
    grid_sync(base, ++nbar);

    for (int t = 0; t < TT; t++) {
        const float* h0r = g_h0[t & 1];
        float*       h0w = g_h0[(t + 1) & 1];
        const float* h1r = g_h1[t & 1];
        float*       h1w = g_h1[(t + 1) & 1];

        if (tid < BB) sidx[tid] = input_batch[tid * TT + t];
        __syncthreads();

        // ================= layer 0: z0 = [x_t | h0] @ W0, K = 1280 =================
        {
            float acc[4][4] = {};
            for (int kt = 0; kt < KL0; kt += KT) {
                #pragma unroll
                for (int i = 0; i < 16; i++) {
                    int lin = tid + i * NTHR;       // 4096 = 128 x 32
                    int m = lin >> 5;
                    int kk = lin & 31;
                    int k = kt + kk;
                    As[kk][m] = (k < EE) ? emb[sidx[m] * EE + k]
                                         : h0r[m * HH + (k - EE)];
                }
                #pragma unroll
                for (int i = 0; i < 4; i++) {
                    int lin = tid + i * NTHR;       // 1024 = 32 x 32
                    int kk = lin >> 5;
                    int n = lin & 31;
                    Bs[kk][n] = W0[(size_t)(kt + kk) * G4H +
                                   ((n >> 3) * HH + cbase + (n & 7))];
                }
                __syncthreads();
                #pragma unroll
                for (int kk = 0; kk < KT; kk++) {
                    float4 a4 = *(const float4*)&As[kk][tm * 4];
                    float4 b4 = *(const float4*)&Bs[kk][tn * 4];
                    float av[4] = {a4.x, a4.y, a4.z, a4.w};
                    float bv[4] = {b4.x, b4.y, b4.z, b4.w};
                    #pragma unroll
                    for (int mi = 0; mi < 4; mi++)
                        #pragma unroll
                        for (int ni = 0; ni < 4; ni++)
                            acc[mi][ni] = fmaf(av[mi], bv[ni], acc[mi][ni]);
                }
                __syncthreads();
            }
            #pragma unroll
            for (int mi = 0; mi < 4; mi++)
                *(float4*)&Zs[tm * 4 + mi][tn * 4] =
                    make_float4(acc[mi][0], acc[mi][1], acc[mi][2], acc[mi][3]);
            __syncthreads();

            // LSTM cell 0 for this CTA's 8 hidden units (all 4 gates local)
            #pragma unroll
            for (int it = 0; it < 4; it++) {
                int item = tid + it * NTHR;         // 1024 = 128 x 8
                int m = item >> 3;
                int kl = item & 7;
                float zi = Zs[m][kl]      + sb0[kl];
                float zj = Zs[m][8 + kl]  + sb0[8 + kl];
                float zf = Zs[m][16 + kl] + sb0[16 + kl];
                float zo = Zs[m][24 + kl] + sb0[24 + kl];
                int gi = m * HH + cbase + kl;
                float c = g_c0[gi];
                float nc = c * sigf(zf + 1.0f) + sigf(zi) * tanhf(zj);
                float nh = tanhf(nc) * sigf(zo);
                g_c0[gi] = nc;
                h0w[gi] = nh;
            }
        }
        grid_sync(base, ++nbar);   // all nh0 visible everywhere

        // ================= layer 1: z1 = [nh0 | h1] @ W1, K = 2048 =================
        {
            float acc[4][4] = {};
            for (int kt = 0; kt < KL1; kt += KT) {
                #pragma unroll
                for (int i = 0; i < 16; i++) {
                    int lin = tid + i * NTHR;
                    int m = lin >> 5;
                    int kk = lin & 31;
                    int k = kt + kk;
                    As[kk][m] = (k < HH) ? h0w[m * HH + k]
                                         : h1r[m * HH + (k - HH)];
                }
                #pragma unroll
                for (int i = 0; i < 4; i++) {
                    int lin = tid + i * NTHR;
                    int kk = lin >> 5;
                    int n = lin & 31;
                    Bs[kk][n] = W1[(size_t)(kt + kk) * G4H +
                                   ((n >> 3) * HH + cbase + (n & 7))];
                }
                __syncthreads();
                #pragma unroll
                for (int kk = 0; kk < KT; kk++) {
                    float4 a4 = *(const float4*)&As[kk][tm * 4];
                    float4 b4 = *(const float4*)&Bs[kk][tn * 4];
                    float av[4] = {a4.x, a4.y, a4.z, a4.w};
                    float bv[4] = {b4.x, b4.y, b4.z, b4.w};
                    #pragma unroll
                    for (int mi = 0; mi < 4; mi++)
                        #pragma unroll
                        for (int ni = 0; ni < 4; ni++)
                            acc[mi][ni] = fmaf(av[mi], bv[ni], acc[mi][ni]);
                }
                __syncthreads();
            }
            #pragma unroll
            for (int mi = 0; mi < 4; mi++)
                *(float4*)&Zs[tm * 4 + mi][tn * 4] =
                    make_float4(acc[mi][0], acc[mi][1], acc[mi][2], acc[mi][3]);
            __syncthreads();

            // LSTM cell 1 + output snapshot at t == len-1
            #pragma unroll
            for (int it = 0; it < 4; it++) {
                int item = tid + it * NTHR;
                int m = item >> 3;
                int kl = item & 7;
                float zi = Zs[m][kl]      + sb1[kl];
                float zj = Zs[m][8 + kl]  + sb1[8 + kl];
                float zf = Zs[m][16 + kl] + sb1[16 + kl];
                float zo = Zs[m][24 + kl] + sb1[24 + kl];
                int gi = m * HH + cbase + kl;
                float c = g_c1[gi];
                float nc = c * sigf(zf + 1.0f) + sigf(zi) * tanhf(zj);
                float nh = tanhf(nc) * sigf(zo);
                g_c1[gi] = nc;
                h1w[gi] = nh;
                if (t == slen[m] - 1) {
                    out[m * HH + cbase + kl] = nh;
                }
            }
        }
        grid_sync(base, ++nbar);   // all nh1 visible before next step
    }
}

extern "C" void kernel_launch(void* const* d_in, const int* in_sizes, int n_in,
                              void* d_out, int out_size) {
    const int*   input_batch   = (const int*)d_in[0];
    const int*   input_lengths = (const int*)d_in[1];
    const float* emb           = (const float*)d_in[2];
    const float* W0            = (const float*)d_in[3];
    const float* b0            = (const float*)d_in[4];
    const float* W1            = (const float*)d_in[5];
    const float* b1            = (const float*)d_in[6];
    float*       out           = (float*)d_out;

    lstm_encoder_kernel<<<NCTA, NTHR>>>(input_batch, input_lengths, emb,
                                        W0, b0, W1, b1, out);
}

// round 2
// speedup vs baseline: 1.0014x; 1.0014x over previous
#include <cuda_runtime.h>
#include <math.h>

// Problem constants
#define BB 128
#define TT 512
#define EE 256
#define HH 1024
#define G4H 4096
#define KL0 1280   // E + H
#define KL1 2048   // 2H
#define NCTA 128
#define NTHR 256
#define KT 32

// -------- persistent device state --------
__device__ float g_h0[2][BB * HH];
__device__ float g_h1[2][BB * HH];
__device__ float g_c0[BB * HH];
__device__ float g_c1[BB * HH];

// grid barrier (self-resetting: count returns to 0 after each barrier,
// gen compared relative to a base read at kernel start -> replay-safe)
__device__ unsigned g_barcnt;
__device__ unsigned g_bargen;

__device__ __forceinline__ void grid_sync(unsigned base, unsigned nbar) {
    __syncthreads();
    if (threadIdx.x == 0) {
        __threadfence();
        unsigned old = atomicAdd(&g_barcnt, 1u);
        if (old == gridDim.x - 1) {
            g_barcnt = 0;
            __threadfence();
            atomicAdd(&g_bargen, 1u);
        } else {
            while ((*(volatile unsigned*)&g_bargen) - base < nbar) {
                __nanosleep(64);
            }
            __threadfence();
        }
    }
    __syncthreads();
}

__device__ __forceinline__ float sigf(float x) {
    return 1.0f / (1.0f + expf(-x));
}

__global__ void __launch_bounds__(NTHR, 1)
lstm_encoder_kernel(const int* __restrict__ input_batch,
                    const int* __restrict__ input_lengths,
                    const float* __restrict__ emb,
                    const float* __restrict__ W0,
                    const float* __restrict__ b0,
                    const float* __restrict__ W1,
                    const float* __restrict__ b1,
                    float* __restrict__ out) {
    __shared__ float As[KT][132];     // k-major A tile, padded
    __shared__ float Bs[KT][32];      // k-major B tile
    __shared__ float Zs[BB][36];      // gate pre-activations for this CTA's 32 cols
    __shared__ int   sidx[BB];
    __shared__ int   slen[BB];
    __shared__ float sb0[32], sb1[32];

    const int tid   = threadIdx.x;
    const int cta   = blockIdx.x;
    const int cbase = cta * 8;        // this CTA owns h columns [cbase, cbase+8)
    const int tm    = tid & 31;       // 32 m-tiles of 4 rows
    const int tn    = tid >> 5;       // 8 n-tiles of 4 cols

    unsigned base = *(volatile unsigned*)&g_bargen;
    unsigned nbar = 0;

    // ---- init state buffers (parity-0 buffers + cell states) ----
    for (int i = cta * NTHR + tid; i < BB * HH; i += NCTA * NTHR) {
        g_h0[0][i] = 0.0f;
        g_h1[0][i] = 0.0f;
        g_c0[i] = 0.0f;
        g_c1[i] = 0.0f;
    }
    if (tid < BB) slen[tid] = input_lengths[tid];
    if (tid < 32) {
        int col = (tid >> 3) * HH + cbase + (tid & 7);
        sb0[tid] = b0[col];
        sb1[tid] = b1[col];
    }
    grid_sync(base, ++nbar);

    for (int t = 0; t < TT; t++) {
        const float* h0r = g_h0[t & 1];
        float*       h0w = g_h0[(t + 1) & 1];
        const float* h1r = g_h1[t & 1];
        float*       h1w = g_h1[(t + 1) & 1];

        if (tid < BB) sidx[tid] = input_batch[tid * TT + t];
        __syncthreads();

        // ================= layer 0: z0 = [x_t | h0] @ W0, K = 1280 =================
        {
            float acc[4][4] = {};
            for (int kt = 0; kt < KL0; kt += KT) {
                #pragma unroll
                for (int i = 0; i < 16; i++) {
                    int lin = tid + i * NTHR;       // 4096 = 128 x 32
                    int m = lin >> 5;
                    int kk = lin & 31;
                    int k = kt + kk;
                    As[kk][m] = (k < EE) ? emb[sidx[m] * EE + k]
                                         : h0r[m * HH + (k - EE)];
                }
                #pragma unroll
                for (int i = 0; i < 4; i++) {
                    int lin = tid + i * NTHR;       // 1024 = 32 x 32
                    int kk = lin >> 5;
                    int n = lin & 31;
                    Bs[kk][n] = W0[(size_t)(kt + kk) * G4H +
                                   ((n >> 3) * HH + cbase + (n & 7))];
                }
                __syncthreads();
                #pragma unroll
                for (int kk = 0; kk < KT; kk++) {
                    float4 a4 = *(const float4*)&As[kk][tm * 4];
                    float4 b4 = *(const float4*)&Bs[kk][tn * 4];
                    float av[4] = {a4.x, a4.y, a4.z, a4.w};
                    float bv[4] = {b4.x, b4.y, b4.z, b4.w};
                    #pragma unroll
                    for (int mi = 0; mi < 4; mi++)
                        #pragma unroll
                        for (int ni = 0; ni < 4; ni++)
                            acc[mi][ni] = fmaf(av[mi], bv[ni], acc[mi][ni]);
                }
                __syncthreads();
            }
            #pragma unroll
            for (int mi = 0; mi < 4; mi++)
                *(float4*)&Zs[tm * 4 + mi][tn * 4] =
                    make_float4(acc[mi][0], acc[mi][1], acc[mi][2], acc[mi][3]);
            __syncthreads();

            // LSTM cell 0 for this CTA's 8 hidden units (all 4 gates local)
            #pragma unroll
            for (int it = 0; it < 4; it++) {
                int item = tid + it * NTHR;         // 1024 = 128 x 8
                int m = item >> 3;
                int kl = item & 7;
                float zi = Zs[m][kl]      + sb0[kl];
                float zj = Zs[m][8 + kl]  + sb0[8 + kl];
                float zf = Zs[m][16 + kl] + sb0[16 + kl];
                float zo = Zs[m][24 + kl] + sb0[24 + kl];
                int gi = m * HH + cbase + kl;
                float c = g_c0[gi];
                float nc = c * sigf(zf + 1.0f) + sigf(zi) * tanhf(zj);
                float nh = tanhf(nc) * sigf(zo);
                g_c0[gi] = nc;
                h0w[gi] = nh;
            }
        }
        grid_sync(base, ++nbar);   // all nh0 visible everywhere

        // ================= layer 1: z1 = [nh0 | h1] @ W1, K = 2048 =================
        {
            float acc[4][4] = {};
            for (int kt = 0; kt < KL1; kt += KT) {
                #pragma unroll
                for (int i = 0; i < 16; i++) {
                    int lin = tid + i * NTHR;
                    int m = lin >> 5;
                    int kk = lin & 31;
                    int k = kt + kk;
                    As[kk][m] = (k < HH) ? h0w[m * HH + k]
                                         : h1r[m * HH + (k - HH)];
                }
                #pragma unroll
                for (int i = 0; i < 4; i++) {
                    int lin = tid + i * NTHR;
                    int kk = lin >> 5;
                    int n = lin & 31;
                    Bs[kk][n] = W1[(size_t)(kt + kk) * G4H +
                                   ((n >> 3) * HH + cbase + (n & 7))];
                }
                __syncthreads();
                #pragma unroll
                for (int kk = 0; kk < KT; kk++) {
                    float4 a4 = *(const float4*)&As[kk][tm * 4];
                    float4 b4 = *(const float4*)&Bs[kk][tn * 4];
                    float av[4] = {a4.x, a4.y, a4.z, a4.w};
                    float bv[4] = {b4.x, b4.y, b4.z, b4.w};
                    #pragma unroll
                    for (int mi = 0; mi < 4; mi++)
                        #pragma unroll
                        for (int ni = 0; ni < 4; ni++)
                            acc[mi][ni] = fmaf(av[mi], bv[ni], acc[mi][ni]);
                }
                __syncthreads();
            }
            #pragma unroll
            for (int mi = 0; mi < 4; mi++)
                *(float4*)&Zs[tm * 4 + mi][tn * 4] =
                    make_float4(acc[mi][0], acc[mi][1], acc[mi][2], acc[mi][3]);
            __syncthreads();

            // LSTM cell 1 + output snapshot at t == len-1
            #pragma unroll
            for (int it = 0; it < 4; it++) {
                int item = tid + it * NTHR;
                int m = item >> 3;
                int kl = item & 7;
                float zi = Zs[m][kl]      + sb1[kl];
                float zj = Zs[m][8 + kl]  + sb1[8 + kl];
                float zf = Zs[m][16 + kl] + sb1[16 + kl];
                float zo = Zs[m][24 + kl] + sb1[24 + kl];
                int gi = m * HH + cbase + kl;
                float c = g_c1[gi];
                float nc = c * sigf(zf + 1.0f) + sigf(zi) * tanhf(zj);
                float nh = tanhf(nc) * sigf(zo);
                g_c1[gi] = nc;
                h1w[gi] = nh;
                if (t == slen[m] - 1) {
                    out[m * HH + cbase + kl] = nh;
                }
            }
        }
        grid_sync(base, ++nbar);   // all nh1 visible before next step
    }
}

extern "C" void kernel_launch(void* const* d_in, const int* in_sizes, int n_in,
                              void* d_out, int out_size) {
    const int*   input_batch   = (const int*)d_in[0];
    const int*   input_lengths = (const int*)d_in[1];
    const float* emb           = (const float*)d_in[2];
    const float* W0            = (const float*)d_in[3];
    const float* b0            = (const float*)d_in[4];
    const float* W1            = (const float*)d_in[5];
    const float* b1            = (const float*)d_in[6];
    float*       out           = (float*)d_out;

    lstm_encoder_kernel<<<NCTA, NTHR>>>(input_batch, input_lengths, emb,
                                        W0, b0, W1, b1, out);
}

// round 3
// speedup vs baseline: 1.0015x; 1.0000x over previous
#include <cuda_runtime.h>
#include <math.h>

// Problem constants
#define BB 128
#define TT 512
#define EE 256
#define HH 1024
#define G4H 4096
#define KL0 1280   // E + H
#define KL1 2048   // 2H
#define NCTA 128
#define NTHR 256
#define KT 32

// -------- persistent device state --------
__device__ float g_h0[2][BB * HH];
__device__ float g_h1[2][BB * HH];
__device__ float g_c0[BB * HH];
__device__ float g_c1[BB * HH];

// grid barrier (self-resetting: count returns to 0 after each barrier,
// gen compared relative to a base read at kernel start -> replay-safe)
__device__ unsigned g_barcnt;
__device__ unsigned g_bargen;

__device__ __forceinline__ void grid_sync(unsigned base, unsigned nbar) {
    __syncthreads();
    if (threadIdx.x == 0) {
        __threadfence();
        unsigned old = atomicAdd(&g_barcnt, 1u);
        if (old == gridDim.x - 1) {
            g_barcnt = 0;
            __threadfence();
            atomicAdd(&g_bargen, 1u);
        } else {
            while ((*(volatile unsigned*)&g_bargen) - base < nbar) {
                __nanosleep(64);
            }
            __threadfence();
        }
    }
    __syncthreads();
}

__device__ __forceinline__ float sigf(float x) {
    return 1.0f / (1.0f + expf(-x));
}

__global__ void __launch_bounds__(NTHR, 1)
lstm_encoder_kernel(const int* __restrict__ input_batch,
                    const int* __restrict__ input_lengths,
                    const float* __restrict__ emb,
                    const float* __restrict__ W0,
                    const float* __restrict__ b0,
                    const float* __restrict__ W1,
                    const float* __restrict__ b1,
                    float* __restrict__ out) {
    __shared__ float As[KT][132];     // k-major A tile, padded
    __shared__ float Bs[KT][32];      // k-major B tile
    __shared__ float Zs[BB][36];      // gate pre-activations for this CTA's 32 cols
    __shared__ int   sidx[BB];
    __shared__ int   slen[BB];
    __shared__ float sb0[32], sb1[32];

    const int tid   = threadIdx.x;
    const int cta   = blockIdx.x;
    const int cbase = cta * 8;        // this CTA owns h columns [cbase, cbase+8)
    const int tm    = tid & 31;       // 32 m-tiles of 4 rows
    const int tn    = tid >> 5;       // 8 n-tiles of 4 cols

    unsigned base = *(volatile unsigned*)&g_bargen;
    unsigned nbar = 0;

    // ---- init state buffers (parity-0 buffers + cell states) ----
    for (int i = cta * NTHR + tid; i < BB * HH; i += NCTA * NTHR) {
        g_h0[0][i] = 0.0f;
        g_h1[0][i] = 0.0f;
        g_c0[i] = 0.0f;
        g_c1[i] = 0.0f;
    }
    if (tid < BB) slen[tid] = input_lengths[tid];
    if (tid < 32) {
        int col = (tid >> 3) * HH + cbase + (tid & 7);
        sb0[tid] = b0[col];
        sb1[tid] = b1[col];
    }
    grid_sync(base, ++nbar);

    for (int t = 0; t < TT; t++) {
        const float* h0r = g_h0[t & 1];
        float*       h0w = g_h0[(t + 1) & 1];
        const float* h1r = g_h1[t & 1];
        float*       h1w = g_h1[(t + 1) & 1];

        if (tid < BB) sidx[tid] = input_batch[tid * TT + t];
        __syncthreads();

        // ================= layer 0: z0 = [x_t | h0] @ W0, K = 1280 =================
        {
            float acc[4][4] = {};
            for (int kt = 0; kt < KL0; kt += KT) {
                #pragma unroll
                for (int i = 0; i < 16; i++) {
                    int lin = tid + i * NTHR;       // 4096 = 128 x 32
                    int m = lin >> 5;
                    int kk = lin & 31;
                    int k = kt + kk;
                    As[kk][m] = (k < EE) ? emb[sidx[m] * EE + k]
                                         : h0r[m * HH + (k - EE)];
                }
                #pragma unroll
                for (int i = 0; i < 4; i++) {
                    int lin = tid + i * NTHR;       // 1024 = 32 x 32
                    int kk = lin >> 5;
                    int n = lin & 31;
                    Bs[kk][n] = W0[(size_t)(kt + kk) * G4H +
                                   ((n >> 3) * HH + cbase + (n & 7))];
                }
                __syncthreads();
                #pragma unroll
                for (int kk = 0; kk < KT; kk++) {
                    float4 a4 = *(const float4*)&As[kk][tm * 4];
                    float4 b4 = *(const float4*)&Bs[kk][tn * 4];
                    float av[4] = {a4.x, a4.y, a4.z, a4.w};
                    float bv[4] = {b4.x, b4.y, b4.z, b4.w};
                    #pragma unroll
                    for (int mi = 0; mi < 4; mi++)
                        #pragma unroll
                        for (int ni = 0; ni < 4; ni++)
                            acc[mi][ni] = fmaf(av[mi], bv[ni], acc[mi][ni]);
                }
                __syncthreads();
            }
            #pragma unroll
            for (int mi = 0; mi < 4; mi++)
                *(float4*)&Zs[tm * 4 + mi][tn * 4] =
                    make_float4(acc[mi][0], acc[mi][1], acc[mi][2], acc[mi][3]);
            __syncthreads();

            // LSTM cell 0 for this CTA's 8 hidden units (all 4 gates local)
            #pragma unroll
            for (int it = 0; it < 4; it++) {
                int item = tid + it * NTHR;         // 1024 = 128 x 8
                int m = item >> 3;
                int kl = item & 7;
                float zi = Zs[m][kl]      + sb0[kl];
                float zj = Zs[m][8 + kl]  + sb0[8 + kl];
                float zf = Zs[m][16 + kl] + sb0[16 + kl];
                float zo = Zs[m][24 + kl] + sb0[24 + kl];
                int gi = m * HH + cbase + kl;
                float c = g_c0[gi];
                float nc = c * sigf(zf + 1.0f) + sigf(zi) * tanhf(zj);
                float nh = tanhf(nc) * sigf(zo);
                g_c0[gi] = nc;
                h0w[gi] = nh;
            }
        }
        grid_sync(base, ++nbar);   // all nh0 visible everywhere

        // ================= layer 1: z1 = [nh0 | h1] @ W1, K = 2048 =================
        {
            float acc[4][4] = {};
            for (int kt = 0; kt < KL1; kt += KT) {
                #pragma unroll
                for (int i = 0; i < 16; i++) {
                    int lin = tid + i * NTHR;
                    int m = lin >> 5;
                    int kk = lin & 31;
                    int k = kt + kk;
                    As[kk][m] = (k < HH) ? h0w[m * HH + k]
                                         : h1r[m * HH + (k - HH)];
                }
                #pragma unroll
                for (int i = 0; i < 4; i++) {
                    int lin = tid + i * NTHR;
                    int kk = lin >> 5;
                    int n = lin & 31;
                    Bs[kk][n] = W1[(size_t)(kt + kk) * G4H +
                                   ((n >> 3) * HH + cbase + (n & 7))];
                }
                __syncthreads();
                #pragma unroll
                for (int kk = 0; kk < KT; kk++) {
                    float4 a4 = *(const float4*)&As[kk][tm * 4];
                    float4 b4 = *(const float4*)&Bs[kk][tn * 4];
                    float av[4] = {a4.x, a4.y, a4.z, a4.w};
                    float bv[4] = {b4.x, b4.y, b4.z, b4.w};
                    #pragma unroll
                    for (int mi = 0; mi < 4; mi++)
                        #pragma unroll
                        for (int ni = 0; ni < 4; ni++)
                            acc[mi][ni] = fmaf(av[mi], bv[ni], acc[mi][ni]);
                }
                __syncthreads();
            }
            #pragma unroll
            for (int mi = 0; mi < 4; mi++)
                *(float4*)&Zs[tm * 4 + mi][tn * 4] =
                    make_float4(acc[mi][0], acc[mi][1], acc[mi][2], acc[mi][3]);
            __syncthreads();

            // LSTM cell 1 + output snapshot at t == len-1
            #pragma unroll
            for (int it = 0; it < 4; it++) {
                int item = tid + it * NTHR;
                int m = item >> 3;
                int kl = item & 7;
                float zi = Zs[m][kl]      + sb1[kl];
                float zj = Zs[m][8 + kl]  + sb1[8 + kl];
                float zf = Zs[m][16 + kl] + sb1[16 + kl];
                float zo = Zs[m][24 + kl] + sb1[24 + kl];
                int gi = m * HH + cbase + kl;
                float c = g_c1[gi];
                float nc = c * sigf(zf + 1.0f) + sigf(zi) * tanhf(zj);
                float nh = tanhf(nc) * sigf(zo);
                g_c1[gi] = nc;
                h1w[gi] = nh;
                if (t == slen[m] - 1) {
                    out[m * HH + cbase + kl] = nh;
                }
            }
        }
        grid_sync(base, ++nbar);   // all nh1 visible before next step
    }
}

extern "C" void kernel_launch(void* const* d_in, const int* in_sizes, int n_in,
                              void* d_out, int out_size) {
    const int*   input_batch   = (const int*)d_in[0];
    const int*   input_lengths = (const int*)d_in[1];
    const float* emb           = (const float*)d_in[2];
    const float* W0            = (const float*)d_in[3];
    const float* b0            = (const float*)d_in[4];
    const float* W1            = (const float*)d_in[5];
    const float* b1            = (const float*)d_in[6];
    float*       out           = (float*)d_out;

    lstm_encoder_kernel<<<NCTA, NTHR>>>(input_batch, input_lengths, emb,
                                        W0, b0, W1, b1, out);
}

// round 5
// speedup vs baseline: 1.5662x; 1.5640x over previous
#include <cuda_runtime.h>
#include <math.h>
#include <stdint.h>

#define BB 128
#define TT 512
#define HH 1024
#define NCTA 128
#define NTHR 256

// ---- persistent device state: packed (bf16-hi, bf16-lo) pairs, pair-major ----
// activations: [pair][row] ; weights: [pair][4096 interleaved gate-cols]
__device__ __align__(16) uint2 g_x [TT][128][BB];   // x: 128 pairs (E=256)
__device__ __align__(16) uint2 g_h0[2][512][BB];    // h0: 512 pairs, double buffered
__device__ __align__(16) uint2 g_h1[2][512][BB];
__device__ __align__(16) uint2 g_w0[640][4096];     // W0^T packed: [kpair][col]
__device__ __align__(16) uint2 g_w1[1024][4096];
__device__ unsigned g_barcnt, g_bargen;

// smem layout (dynamic):
//  As:  2 x [32 pairs][128 rows] uint2 (xor-swizzled rows)      [0, 65536)
//  Bs:  2 x [4 s][4 nt][32 lane][4 words] uint32 (frag layout)  [65536, 81920)
//  Zs:  float [128][36]                                          [81920, 100352)
//  sb:  float sb0[64], sb1[64]                                   [100352, 100864)
#define SMEM_DYN 100864

__device__ __forceinline__ float sigf(float x) { return 1.0f / (1.0f + expf(-x)); }

__device__ __forceinline__ uint2 pack_pair(float e0, float e1) {
    uint32_t hi, lo;
    asm("cvt.rn.bf16x2.f32 %0, %1, %2;" : "=r"(hi) : "f"(e1), "f"(e0)); // low = e0
    float r0 = e0 - __uint_as_float(hi << 16);
    float r1 = e1 - __uint_as_float(hi & 0xFFFF0000u);
    asm("cvt.rn.bf16x2.f32 %0, %1, %2;" : "=r"(lo) : "f"(r1), "f"(r0));
    return make_uint2(hi, lo);
}

__device__ __forceinline__ void bmma(float* c, uint32_t a0, uint32_t a1, uint32_t a2,
                                     uint32_t a3, uint32_t b0, uint32_t b1) {
    asm("mma.sync.aligned.m16n8k16.row.col.f32.bf16.bf16.f32 "
        "{%0,%1,%2,%3},{%4,%5,%6,%7},{%8,%9},{%0,%1,%2,%3};"
        : "+f"(c[0]), "+f"(c[1]), "+f"(c[2]), "+f"(c[3])
        : "r"(a0), "r"(a1), "r"(a2), "r"(a3), "r"(b0), "r"(b1));
}

__device__ __forceinline__ void grid_sync(unsigned base, unsigned nbar) {
    __syncthreads();
    if (threadIdx.x == 0) {
        __threadfence();
        unsigned old = atomicAdd(&g_barcnt, 1u);
        if (old == gridDim.x - 1) {
            g_barcnt = 0;
            __threadfence();
            atomicAdd(&g_bargen, 1u);
        } else {
            while ((*(volatile unsigned*)&g_bargen) - base < nbar) { __nanosleep(64); }
            __threadfence();
        }
    }
    __syncthreads();
}

// ---- prep: embeddings -> g_x ----
__global__ void prep_x(const int* __restrict__ ib, const float* __restrict__ emb) {
    const int N = TT * 128 * BB;
    for (int i = blockIdx.x * blockDim.x + threadIdx.x; i < N;
         i += gridDim.x * blockDim.x) {
        int m = i & 127;
        int p = (i >> 7) & 127;
        int t = i >> 14;
        const float* s = emb + (size_t)ib[m * TT + t] * 256 + 2 * p;
        g_x[t][p][m] = pack_pair(s[0], s[1]);
    }
}

// ---- prep: W -> packed transposed interleaved ----
__global__ void prep_w(const float* __restrict__ W0, const float* __restrict__ W1) {
    const long n0 = 640L * 4096, n1 = 1024L * 4096;
    for (long i = (long)blockIdx.x * blockDim.x + threadIdx.x; i < n0 + n1;
         i += (long)gridDim.x * blockDim.x) {
        long j = i;
        const float* W = W0;
        uint2* dst = &g_w0[0][0];
        if (j >= n0) { j -= n0; W = W1; dst = &g_w1[0][0]; }
        int P = (int)(j >> 12);
        int c = (int)(j & 4095);
        int gcol = ((c >> 3) & 3) * HH + (c >> 5) * 8 + (c & 7);
        float e0 = W[(size_t)(2 * P) * 4096 + gcol];
        float e1 = W[(size_t)(2 * P + 1) * 4096 + gcol];
        dst[(size_t)P * 4096 + c] = pack_pair(e0, e1);
    }
}

__global__ void __launch_bounds__(NTHR, 1)
lstm_main(const int* __restrict__ il,
          const float* __restrict__ b0g,
          const float* __restrict__ b1g,
          float* __restrict__ out) {
    extern __shared__ char smem[];
    uint2*    As  = (uint2*)smem;                     // [bp][p][r]: bp*4096 + p*128 + r
    uint32_t* Bsw = (uint32_t*)(smem + 65536);        // [bp][s][nt][lane][w]
    float*    Zs  = (float*)(smem + 81920);           // [r][36]
    float*    sb0 = (float*)(smem + 100352);
    float*    sb1 = sb0 + 64;

    const int tid = threadIdx.x;
    const int wid = tid >> 5, lid = tid & 31;
    const int cta = blockIdx.x;
    const int g   = lid >> 2, tg = lid & 3;

    unsigned bbase = *(volatile unsigned*)&g_bargen;
    unsigned nbar = 0;

    if (tid < 32) {
        int gc = (tid >> 3) * HH + cta * 8 + (tid & 7);
        sb0[tid] = b0g[gc];
        sb1[tid] = b1g[gc];
    }
    {   // zero parity-0 h buffers
        uint2 z2 = make_uint2(0u, 0u);
        uint2* z0 = &g_h0[0][0][0];
        uint2* z1 = &g_h1[0][0][0];
        for (int i = cta * NTHR + tid; i < 512 * BB; i += NCTA * NTHR) { z0[i] = z2; z1[i] = z2; }
    }

    // cell state (fp32, registers): thread owns row m = tid>>1, units uh..uh+3
    const int m  = tid >> 1;
    const int uh = (tid & 1) * 4;
    float cs0[4] = {0.f, 0.f, 0.f, 0.f};
    float cs1[4] = {0.f, 0.f, 0.f, 0.f};
    const int mylen = il[m];

    grid_sync(bbase, ++nbar);

    for (int t = 0; t < TT; t++) {
        const int pr = t & 1, pw = pr ^ 1;
        for (int layer = 0; layer < 2; layer++) {
            const int nch = layer ? 32 : 20;

            float C[2][4][4];
#pragma unroll
            for (int a = 0; a < 2; a++)
#pragma unroll
                for (int b = 0; b < 4; b++)
#pragma unroll
                    for (int d = 0; d < 4; d++) C[a][b][d] = 0.f;

            for (int ch = 0; ch < nch + 1; ch++) {
                // ---- loaders: fill buffer (ch)&1 with chunk ch (shifted pipeline) ----
                if (wid >= 4 && ch < nch) {
                    const int lt = tid - 128;
                    const int bp = ch & 1;
                    // select A source for this chunk
                    const uint2* ap;
                    if (layer == 0)
                        ap = (ch < 4) ? &g_x[t][ch * 32][0] : &g_h0[pr][ch * 32 - 128][0];
                    else
                        ap = (ch < 16) ? &g_h0[pw][ch * 32][0] : &g_h1[pr][ch * 32 - 512][0];
                    const uint2* bw = (layer ? &g_w1[0][0] : &g_w0[0][0])
                                      + (size_t)(ch * 32) * 4096 + cta * 32;
                    // A: thread -> pair p = lt>>2, row quarter q = lt&3
                    {
                        const int p = lt >> 2, q = lt & 3;
                        const uint2* srcA = ap + (size_t)p * 128;
                        uint2* dstA = As + bp * 4096 + p * 128;
                        const int x = (p & 3) << 2;
#pragma unroll
                        for (int i = 0; i < 16; i++) {
                            int r = q * 32 + 2 * i;
                            float4 v = *(const float4*)(srcA + r);
                            *(float4*)(dstA + (r ^ x)) = v;
                        }
                    }
                    // B: thread -> pair p = lt>>2, col-quad cq = lt&3 (cols cq*8 + 2j)
                    {
                        const int p = lt >> 2, cq = lt & 3;
                        const int s = p >> 3, qq = p & 7, tg2 = qq & 3, slot = qq >> 2;
                        uint32_t* bb = Bsw + bp * 2048 + (s * 4) * 128;
#pragma unroll
                        for (int j = 0; j < 4; j++) {
                            int c = cq * 8 + 2 * j;
                            uint4 v = *(const uint4*)(bw + (size_t)p * 4096 + c);
                            int nt = c >> 3, gg = c & 7;
                            uint32_t* d0 = bb + (nt * 32 + 4 * gg + tg2) * 4;
                            d0[slot]      = v.x;  // hi(c)
                            d0[slot + 2]  = v.y;  // lo(c)
                            d0[16 + slot]     = v.z;  // hi(c+1) -> lane+4
                            d0[16 + slot + 2] = v.w;  // lo(c+1)
                        }
                    }
                }
                // ---- computers: mma over buffer (ch-1)&1 ----
                if (wid < 4 && ch > 0) {
                    const int bp = (ch - 1) & 1;
                    const uint2* Ab = As + bp * 4096;
                    const uint32_t* Bb = Bsw + bp * 2048;
#pragma unroll
                    for (int s = 0; s < 4; s++) {
                        uint4 Bf[4];
#pragma unroll
                        for (int nt = 0; nt < 4; nt++)
                            Bf[nt] = *(const uint4*)(Bb + ((s * 4 + nt) * 32 + lid) * 4);
#pragma unroll
                        for (int rt = 0; rt < 2; rt++) {
                            const int R = wid * 32 + rt * 16;
                            const int x = tg << 2;
                            uint2 a0 = Ab[(s * 8 + tg) * 128 + ((R + g) ^ x)];
                            uint2 a1 = Ab[(s * 8 + tg) * 128 + ((R + g + 8) ^ x)];
                            uint2 a2 = Ab[(s * 8 + 4 + tg) * 128 + ((R + g) ^ x)];
                            uint2 a3 = Ab[(s * 8 + 4 + tg) * 128 + ((R + g + 8) ^ x)];
#pragma unroll
                            for (int nt = 0; nt < 4; nt++) {
                                bmma(C[rt][nt], a0.x, a1.x, a2.x, a3.x, Bf[nt].x, Bf[nt].y);
                                bmma(C[rt][nt], a0.y, a1.y, a2.y, a3.y, Bf[nt].x, Bf[nt].y);
                                bmma(C[rt][nt], a0.x, a1.x, a2.x, a3.x, Bf[nt].z, Bf[nt].w);
                            }
                        }
                    }
                }
                __syncthreads();
            }

            // ---- epilogue: C -> Zs ----
            if (wid < 4) {
#pragma unroll
                for (int rt = 0; rt < 2; rt++) {
                    const int r = wid * 32 + rt * 16 + g;
#pragma unroll
                    for (int nt = 0; nt < 4; nt++) {
                        const int col = nt * 8 + 2 * tg;
                        *(float2*)&Zs[r * 36 + col]       = make_float2(C[rt][nt][0], C[rt][nt][1]);
                        *(float2*)&Zs[(r + 8) * 36 + col] = make_float2(C[rt][nt][2], C[rt][nt][3]);
                    }
                }
            }
            __syncthreads();

            // ---- cell: all 256 threads, 4 units each ----
            {
                const float* sb = layer ? sb1 : sb0;
                float* cs = layer ? cs1 : cs0;
                float4 vi = *(float4*)&Zs[m * 36 + 0 + uh];
                float4 vj = *(float4*)&Zs[m * 36 + 8 + uh];
                float4 vf = *(float4*)&Zs[m * 36 + 16 + uh];
                float4 vo = *(float4*)&Zs[m * 36 + 24 + uh];
                float ziv[4] = {vi.x, vi.y, vi.z, vi.w};
                float zjv[4] = {vj.x, vj.y, vj.z, vj.w};
                float zfv[4] = {vf.x, vf.y, vf.z, vf.w};
                float zov[4] = {vo.x, vo.y, vo.z, vo.w};
                float nh[4];
#pragma unroll
                for (int j = 0; j < 4; j++) {
                    float zi = ziv[j] + sb[uh + j];
                    float zj = zjv[j] + sb[8 + uh + j];
                    float zf = zfv[j] + sb[16 + uh + j];
                    float zo = zov[j] + sb[24 + uh + j];
                    float nc = cs[j] * sigf(zf + 1.0f) + sigf(zi) * tanhf(zj);
                    nh[j] = tanhf(nc) * sigf(zo);
                    cs[j] = nc;
                }
                uint2 p0 = pack_pair(nh[0], nh[1]);
                uint2 p1 = pack_pair(nh[2], nh[3]);
                const int pg = cta * 4 + (tid & 1) * 2;
                if (layer == 0) {
                    g_h0[pw][pg][m] = p0;
                    g_h0[pw][pg + 1][m] = p1;
                } else {
                    g_h1[pw][pg][m] = p0;
                    g_h1[pw][pg + 1][m] = p1;
                    if (t == mylen - 1)
                        *(float4*)&out[m * HH + cta * 8 + uh] =
                            make_float4(nh[0], nh[1], nh[2], nh[3]);
                }
            }
            grid_sync(bbase, ++nbar);
        }
    }
}

extern "C" void kernel_launch(void* const* d_in, const int* in_sizes, int n_in,
                              void* d_out, int out_size) {
    const int*   input_batch   = (const int*)d_in[0];
    const int*   input_lengths = (const int*)d_in[1];
    const float* emb           = (const float*)d_in[2];
    const float* W0            = (const float*)d_in[3];
    const float* b0            = (const float*)d_in[4];
    const float* W1            = (const float*)d_in[5];
    const float* b1            = (const float*)d_in[6];
    float*       out           = (float*)d_out;

    cudaFuncSetAttribute(lstm_main, cudaFuncAttributeMaxDynamicSharedMemorySize, SMEM_DYN);
    prep_x<<<1024, 256>>>(input_batch, emb);
    prep_w<<<2048, 256>>>(W0, W1);
    lstm_main<<<NCTA, NTHR, SMEM_DYN>>>(input_lengths, b0, b1, out);
}

// round 6
// speedup vs baseline: 2.1447x; 1.3693x over previous
#include <cuda_runtime.h>
#include <math.h>
#include <stdint.h>

#define BB 128
#define TT 512
#define HH 1024
#define NCTA 128
#define NTHR 256
#define NSTG 4

// smem layout (dynamic):
//   stage s in [0,4): A tile 32KB @ s*40960, B tile 8KB @ s*40960+32768
//   Zs  float[128][36]  @ 163840   (18432 B)
//   sb0 float[32] @ 182272, sb1 float[32] @ 182400
//   mbarriers @ 182784: full(s)=+s*16, empty(s)=+s*16+8
#define ZS_OFF   163840
#define SB_OFF   182272
#define MB_OFF   182784
#define FULL_MB(s)  (MB_OFF + (s) * 16)
#define EMPTY_MB(s) (MB_OFF + (s) * 16 + 8)
#define SMEM_DYN 183296

// ---- persistent device state: packed (bf16-hi, bf16-lo) pairs ----
// activations: [pair][row]; weights: [chunk][cta-block][pair32][col32]
__device__ __align__(16) uint2 g_x [TT][128][BB];
__device__ __align__(16) uint2 g_h0[2][512][BB];
__device__ __align__(16) uint2 g_h1[2][512][BB];
__device__ __align__(16) uint2 g_w0[20][128][32][32];
__device__ __align__(16) uint2 g_w1[32][128][32][32];
__device__ unsigned g_barcnt, g_bargen;

__device__ __forceinline__ float sigf(float x) { return 1.0f / (1.0f + expf(-x)); }

__device__ __forceinline__ uint32_t s2u(const void* p) {
    uint32_t a;
    asm("{ .reg .u64 t; cvta.to.shared.u64 t, %1; cvt.u32.u64 %0, t; }" : "=r"(a) : "l"(p));
    return a;
}
__device__ __forceinline__ uint2 pack_pair(float e0, float e1) {
    uint32_t hi, lo;
    asm("cvt.rn.bf16x2.f32 %0, %1, %2;" : "=r"(hi) : "f"(e1), "f"(e0));
    float r0 = e0 - __uint_as_float(hi << 16);
    float r1 = e1 - __uint_as_float(hi & 0xFFFF0000u);
    asm("cvt.rn.bf16x2.f32 %0, %1, %2;" : "=r"(lo) : "f"(r1), "f"(r0));
    return make_uint2(hi, lo);
}
__device__ __forceinline__ void bmma(float* c, uint32_t a0, uint32_t a1, uint32_t a2,
                                     uint32_t a3, uint32_t b0, uint32_t b1) {
    asm("mma.sync.aligned.m16n8k16.row.col.f32.bf16.bf16.f32 "
        "{%0,%1,%2,%3},{%4,%5,%6,%7},{%8,%9},{%0,%1,%2,%3};"
        : "+f"(c[0]), "+f"(c[1]), "+f"(c[2]), "+f"(c[3])
        : "r"(a0), "r"(a1), "r"(a2), "r"(a3), "r"(b0), "r"(b1));
}
__device__ __forceinline__ void mbar_init(uint32_t b, uint32_t n) {
    asm volatile("mbarrier.init.shared.b64 [%0], %1;" :: "r"(b), "r"(n) : "memory");
}
__device__ __forceinline__ void mexpect(uint32_t b, uint32_t tx) {
    asm volatile("mbarrier.arrive.expect_tx.shared.b64 _, [%0], %1;" :: "r"(b), "r"(tx) : "memory");
}
__device__ __forceinline__ void marrive(uint32_t b) {
    asm volatile("mbarrier.arrive.shared.b64 _, [%0];" :: "r"(b) : "memory");
}
__device__ __forceinline__ void mwait(uint32_t b, uint32_t ph) {
    asm volatile(
        "{\n\t.reg .pred P;\n"
        "W_%=:\n\t"
        "mbarrier.try_wait.parity.acquire.cta.shared::cta.b64 P, [%0], %1, 0x989680;\n\t"
        "@P bra D_%=;\n\t"
        "bra W_%=;\n"
        "D_%=:\n\t}"
        :: "r"(b), "r"(ph) : "memory");
}
__device__ __forceinline__ void bulk(uint32_t dst, const void* src, uint32_t bytes, uint32_t mbar) {
    asm volatile("cp.async.bulk.shared::cluster.global.mbarrier::complete_tx::bytes [%0], [%1], %2, [%3];"
        :: "r"(dst), "l"(src), "r"(bytes), "r"(mbar) : "memory");
}
__device__ __forceinline__ void grid_sync(unsigned base, unsigned nbar) {
    __syncthreads();
    if (threadIdx.x == 0) {
        __threadfence();
        unsigned old = atomicAdd(&g_barcnt, 1u);
        if (old == gridDim.x - 1) {
            g_barcnt = 0;
            __threadfence();
            atomicAdd(&g_bargen, 1u);
        } else {
            while ((*(volatile unsigned*)&g_bargen) - base < nbar) { __nanosleep(64); }
            __threadfence();
        }
    }
    __syncthreads();
}

// ---- prep: embeddings -> g_x ----
__global__ void prep_x(const int* __restrict__ ib, const float* __restrict__ emb) {
    const int N = TT * 128 * BB;
    for (int i = blockIdx.x * blockDim.x + threadIdx.x; i < N;
         i += gridDim.x * blockDim.x) {
        int m = i & 127;
        int p = (i >> 7) & 127;
        int t = i >> 14;
        const float* s = emb + (size_t)ib[m * TT + t] * 256 + 2 * p;
        g_x[t][p][m] = pack_pair(s[0], s[1]);
    }
}

// ---- prep: W -> packed [chunk][cb][pair][col] ----
__global__ void prep_w(const float* __restrict__ W0, const float* __restrict__ W1) {
    const long n0 = 20L * 131072, n1 = 32L * 131072;
    for (long i = (long)blockIdx.x * blockDim.x + threadIdx.x; i < n0 + n1;
         i += (long)gridDim.x * blockDim.x) {
        long j = i;
        const float* W = W0;
        uint2* dst = &g_w0[0][0][0][0];
        if (j >= n0) { j -= n0; W = W1; dst = &g_w1[0][0][0][0]; }
        int c  = (int)(j & 31);
        int p  = (int)((j >> 5) & 31);
        int cb = (int)((j >> 10) & 127);
        int ch = (int)(j >> 17);
        int gcol = ((c >> 3) & 3) * HH + cb * 8 + (c & 7);
        int k0 = 2 * (ch * 32 + p);
        dst[j] = pack_pair(W[(size_t)k0 * 4096 + gcol],
                           W[(size_t)(k0 + 1) * 4096 + gcol]);
    }
}

__global__ void __launch_bounds__(NTHR, 1)
lstm_main(const int* __restrict__ il,
          const float* __restrict__ b0g,
          const float* __restrict__ b1g,
          float* __restrict__ out) {
    extern __shared__ char smem[];
    float* Zs  = (float*)(smem + ZS_OFF);
    float* sb0 = (float*)(smem + SB_OFF);
    float* sb1 = (float*)(smem + SB_OFF + 128);
    const uint32_t sbase = s2u(smem);

    const int tid = threadIdx.x;
    const int wid = tid >> 5, lid = tid & 31;
    const int cta = blockIdx.x;
    const int g = lid >> 2, q = lid & 3;
    const int R = wid * 16;

    unsigned bbase = *(volatile unsigned*)&g_bargen;
    unsigned nbar = 0;

    if (tid == 0) {
        for (int s = 0; s < NSTG; s++) {
            mbar_init(sbase + FULL_MB(s), 1);
            mbar_init(sbase + EMPTY_MB(s), 8);
        }
    }
    if (tid < 32) {
        int gc = (tid >> 3) * HH + cta * 8 + (tid & 7);
        sb0[tid] = b0g[gc];
        sb1[tid] = b1g[gc];
    }
    {   // zero parity-0 h buffers
        uint2 z2 = make_uint2(0u, 0u);
        uint2* z0 = &g_h0[0][0][0];
        uint2* z1 = &g_h1[0][0][0];
        for (int i = cta * NTHR + tid; i < 512 * BB; i += NCTA * NTHR) { z0[i] = z2; z1[i] = z2; }
    }

    // cell state (fp32 registers): thread owns row m, units uh..uh+3
    const int m  = tid >> 1;
    const int uh = (tid & 1) * 4;
    float cs0[4] = {0.f, 0.f, 0.f, 0.f};
    float cs1[4] = {0.f, 0.f, 0.f, 0.f};
    const int mylen = il[m];

    int pstg = 0, pph = 1;   // producer ring (tid0 only)
    int cstg = 0, cph = 0;   // consumer ring

    grid_sync(bbase, ++nbar);

    for (int t = 0; t < TT; t++) {
        const int pr = t & 1, pw = pr ^ 1;
        for (int layer = 0; layer < 2; layer++) {
            const int nc = layer ? 32 : 20;

            auto issue = [&](int c) {
                mwait(sbase + EMPTY_MB(pstg), (unsigned)pph);
                mexpect(sbase + FULL_MB(pstg), 40960u);
                const uint2* ap;
                const uint2* bp_;
                if (layer == 0) {
                    ap  = (c < 4) ? &g_x[t][c * 32][0] : &g_h0[pr][c * 32 - 128][0];
                    bp_ = &g_w0[c][cta][0][0];
                } else {
                    ap  = (c < 16) ? &g_h0[pw][c * 32][0] : &g_h1[pr][(c - 16) * 32][0];
                    bp_ = &g_w1[c][cta][0][0];
                }
                bulk(sbase + pstg * 40960, ap, 32768u, sbase + FULL_MB(pstg));
                bulk(sbase + pstg * 40960 + 32768, bp_, 8192u, sbase + FULL_MB(pstg));
                if (++pstg == NSTG) { pstg = 0; pph ^= 1; }
            };

            float C[4][4];
#pragma unroll
            for (int a = 0; a < 4; a++)
#pragma unroll
                for (int d = 0; d < 4; d++) C[a][d] = 0.f;

            if (tid == 0) {
                for (int i = 0; i < NSTG - 1 && i < nc; i++) issue(i);
            }

            for (int ch = 0; ch < nc; ch++) {
                if (tid == 0 && ch + NSTG - 1 < nc) issue(ch + NSTG - 1);

                mwait(sbase + FULL_MB(cstg), (unsigned)cph);
                const uint2* Ab = (const uint2*)(smem + cstg * 40960);
                const uint2* Bb = (const uint2*)(smem + cstg * 40960 + 32768);
#pragma unroll
                for (int s = 0; s < 4; s++) {
                    uint2 a0 = Ab[(s * 8 + q) * 128 + R + g];
                    uint2 a1 = Ab[(s * 8 + q) * 128 + R + g + 8];
                    uint2 a2 = Ab[(s * 8 + q + 4) * 128 + R + g];
                    uint2 a3 = Ab[(s * 8 + q + 4) * 128 + R + g + 8];
#pragma unroll
                    for (int nt = 0; nt < 4; nt++) {
                        uint2 B0 = Bb[(s * 8 + q) * 32 + nt * 8 + g];
                        uint2 B1 = Bb[(s * 8 + q + 4) * 32 + nt * 8 + g];
                        bmma(C[nt], a0.x, a1.x, a2.x, a3.x, B0.x, B1.x);
                        bmma(C[nt], a0.y, a1.y, a2.y, a3.y, B0.x, B1.x);
                        bmma(C[nt], a0.x, a1.x, a2.x, a3.x, B0.y, B1.y);
                    }
                }
                __syncwarp();
                if (lid == 0) marrive(sbase + EMPTY_MB(cstg));
                if (++cstg == NSTG) { cstg = 0; cph ^= 1; }
            }

            // epilogue: C -> Zs
#pragma unroll
            for (int nt = 0; nt < 4; nt++) {
                const int col = nt * 8 + 2 * q;
                *(float2*)&Zs[(R + g) * 36 + col]     = make_float2(C[nt][0], C[nt][1]);
                *(float2*)&Zs[(R + g + 8) * 36 + col] = make_float2(C[nt][2], C[nt][3]);
            }
            __syncthreads();

            // cell: all 256 threads, 4 units each
            {
                const float* sb = layer ? sb1 : sb0;
                float* cs = layer ? cs1 : cs0;
                float4 vi = *(float4*)&Zs[m * 36 + 0 + uh];
                float4 vj = *(float4*)&Zs[m * 36 + 8 + uh];
                float4 vf = *(float4*)&Zs[m * 36 + 16 + uh];
                float4 vo = *(float4*)&Zs[m * 36 + 24 + uh];
                float ziv[4] = {vi.x, vi.y, vi.z, vi.w};
                float zjv[4] = {vj.x, vj.y, vj.z, vj.w};
                float zfv[4] = {vf.x, vf.y, vf.z, vf.w};
                float zov[4] = {vo.x, vo.y, vo.z, vo.w};
                float nh[4];
#pragma unroll
                for (int j = 0; j < 4; j++) {
                    float zi = ziv[j] + sb[uh + j];
                    float zj = zjv[j] + sb[8 + uh + j];
                    float zf = zfv[j] + sb[16 + uh + j];
                    float zo = zov[j] + sb[24 + uh + j];
                    float nc = cs[j] * sigf(zf + 1.0f) + sigf(zi) * tanhf(zj);
                    nh[j] = tanhf(nc) * sigf(zo);
                    cs[j] = nc;
                }
                uint2 p0 = pack_pair(nh[0], nh[1]);
                uint2 p1 = pack_pair(nh[2], nh[3]);
                const int pg = cta * 4 + (tid & 1) * 2;
                if (layer == 0) {
                    g_h0[pw][pg][m] = p0;
                    g_h0[pw][pg + 1][m] = p1;
                } else {
                    g_h1[pw][pg][m] = p0;
                    g_h1[pw][pg + 1][m] = p1;
                    if (t == mylen - 1)
                        *(float4*)&out[m * HH + cta * 8 + uh] =
                            make_float4(nh[0], nh[1], nh[2], nh[3]);
                }
            }
            grid_sync(bbase, ++nbar);
        }
    }
}

extern "C" void kernel_launch(void* const* d_in, const int* in_sizes, int n_in,
                              void* d_out, int out_size) {
    const int*   input_batch   = (const int*)d_in[0];
    const int*   input_lengths = (const int*)d_in[1];
    const float* emb           = (const float*)d_in[2];
    const float* W0            = (const float*)d_in[3];
    const float* b0            = (const float*)d_in[4];
    const float* W1            = (const float*)d_in[5];
    const float* b1            = (const float*)d_in[6];
    float*       out           = (float*)d_out;

    cudaFuncSetAttribute(lstm_main, cudaFuncAttributeMaxDynamicSharedMemorySize, SMEM_DYN);
    prep_x<<<1024, 256>>>(input_batch, emb);
    prep_w<<<2048, 256>>>(W0, W1);
    lstm_main<<<NCTA, NTHR, SMEM_DYN>>>(input_lengths, b0, b1, out);
}

// round 7
// speedup vs baseline: 4.0834x; 1.9040x over previous
#include <cuda_runtime.h>
#include <math.h>
#include <stdint.h>

#define BB 128
#define TT 512
#define HH 1024
#define NCTA 128
#define NTHR 256
#define NSTG 4

// smem: stage s: A 32KB @ s*40960, B 8KB @ s*40960+32768
//       Zs float[128][36] @163840; sb @182272; mbars @182784
#define ZS_OFF   163840
#define SB_OFF   182272
#define MB_OFF   182784
#define FULL_MB(s)  (MB_OFF + (s) * 16)
#define EMPTY_MB(s) (MB_OFF + (s) * 16 + 8)
#define SMEM_DYN 183296

// ---- persistent device state: packed (bf16-hi, bf16-lo) pairs ----
// A images swizzled: [p][m] stored at row m ^ ((p&3)<<2)
// B images swizzled: [ch][cb][p][c] stored at col c ^ ((p&3)<<2)
__device__ __align__(16) uint2 g_x [TT][128][BB];
__device__ __align__(16) uint2 g_h0[2][512][BB];
__device__ __align__(16) uint2 g_h1[2][512][BB];
__device__ __align__(16) uint2 g_w0[20][128][32][32];
__device__ __align__(16) uint2 g_w1[32][128][32][32];
__device__ unsigned g_barcnt, g_bargen;

__device__ __forceinline__ float sigf(float x) { return 1.0f / (1.0f + expf(-x)); }

__device__ __forceinline__ uint32_t s2u(const void* p) {
    uint32_t a;
    asm("{ .reg .u64 t; cvta.to.shared.u64 t, %1; cvt.u32.u64 %0, t; }" : "=r"(a) : "l"(p));
    return a;
}
__device__ __forceinline__ uint2 pack_pair(float e0, float e1) {
    uint32_t hi, lo;
    asm("cvt.rn.bf16x2.f32 %0, %1, %2;" : "=r"(hi) : "f"(e1), "f"(e0));
    float r0 = e0 - __uint_as_float(hi << 16);
    float r1 = e1 - __uint_as_float(hi & 0xFFFF0000u);
    asm("cvt.rn.bf16x2.f32 %0, %1, %2;" : "=r"(lo) : "f"(r1), "f"(r0));
    return make_uint2(hi, lo);
}
__device__ __forceinline__ void bmma(float* c, uint32_t a0, uint32_t a1, uint32_t a2,
                                     uint32_t a3, uint32_t b0, uint32_t b1) {
    asm("mma.sync.aligned.m16n8k16.row.col.f32.bf16.bf16.f32 "
        "{%0,%1,%2,%3},{%4,%5,%6,%7},{%8,%9},{%0,%1,%2,%3};"
        : "+f"(c[0]), "+f"(c[1]), "+f"(c[2]), "+f"(c[3])
        : "r"(a0), "r"(a1), "r"(a2), "r"(a3), "r"(b0), "r"(b1));
}
__device__ __forceinline__ void mbar_init(uint32_t b, uint32_t n) {
    asm volatile("mbarrier.init.shared.b64 [%0], %1;" :: "r"(b), "r"(n) : "memory");
}
__device__ __forceinline__ void mexpect(uint32_t b, uint32_t tx) {
    asm volatile("mbarrier.arrive.expect_tx.shared.b64 _, [%0], %1;" :: "r"(b), "r"(tx) : "memory");
}
__device__ __forceinline__ void marrive(uint32_t b) {
    asm volatile("mbarrier.arrive.shared.b64 _, [%0];" :: "r"(b) : "memory");
}
__device__ __forceinline__ void mwait(uint32_t b, uint32_t ph) {
    asm volatile(
        "{\n\t.reg .pred P;\n"
        "W_%=:\n\t"
        "mbarrier.try_wait.parity.acquire.cta.shared::cta.b64 P, [%0], %1, 0x989680;\n\t"
        "@P bra D_%=;\n\t"
        "bra W_%=;\n"
        "D_%=:\n\t}"
        :: "r"(b), "r"(ph) : "memory");
}
__device__ __forceinline__ void bulk(uint32_t dst, const void* src, uint32_t bytes, uint32_t mbar) {
    asm volatile("cp.async.bulk.shared::cluster.global.mbarrier::complete_tx::bytes [%0], [%1], %2, [%3];"
        :: "r"(dst), "l"(src), "r"(bytes), "r"(mbar) : "memory");
}
__device__ __forceinline__ void grid_sync(unsigned base, unsigned nbar) {
    __syncthreads();
    if (threadIdx.x == 0) {
        __threadfence();
        unsigned old = atomicAdd(&g_barcnt, 1u);
        if (old == gridDim.x - 1) {
            g_barcnt = 0;
            __threadfence();
            atomicAdd(&g_bargen, 1u);
        } else {
            while ((*(volatile unsigned*)&g_bargen) - base < nbar) { __nanosleep(64); }
            __threadfence();
        }
    }
    __syncthreads();
}

// ---- prep: embeddings -> g_x (A-swizzled) ----
__global__ void prep_x(const int* __restrict__ ib, const float* __restrict__ emb) {
    const int N = TT * 128 * BB;
    for (int i = blockIdx.x * blockDim.x + threadIdx.x; i < N;
         i += gridDim.x * blockDim.x) {
        int m = i & 127;
        int p = (i >> 7) & 127;
        int t = i >> 14;
        const float* s = emb + (size_t)ib[m * TT + t] * 256 + 2 * p;
        g_x[t][p][m ^ ((p & 3) << 2)] = pack_pair(s[0], s[1]);
    }
}

// ---- prep: W -> packed [chunk][cb][p][c'] (B-swizzled) ----
__global__ void prep_w(const float* __restrict__ W0, const float* __restrict__ W1) {
    const long n0 = 20L * 131072, n1 = 32L * 131072;
    for (long i = (long)blockIdx.x * blockDim.x + threadIdx.x; i < n0 + n1;
         i += (long)gridDim.x * blockDim.x) {
        long j = i;
        const float* W = W0;
        uint2* dst = &g_w0[0][0][0][0];
        if (j >= n0) { j -= n0; W = W1; dst = &g_w1[0][0][0][0]; }
        int c  = (int)(j & 31);
        int p  = (int)((j >> 5) & 31);
        int cb = (int)((j >> 10) & 127);
        int ch = (int)(j >> 17);
        int gcol = ((c >> 3) & 3) * HH + cb * 8 + (c & 7);
        int k0 = 2 * (ch * 32 + p);
        dst[(j & ~31L) | (long)(c ^ ((p & 3) << 2))] =
            pack_pair(W[(size_t)k0 * 4096 + gcol],
                      W[(size_t)(k0 + 1) * 4096 + gcol]);
    }
}

__global__ void __launch_bounds__(NTHR, 1)
lstm_main(const int* __restrict__ il,
          const float* __restrict__ b0g,
          const float* __restrict__ b1g,
          float* __restrict__ out) {
    extern __shared__ char smem[];
    float* Zs  = (float*)(smem + ZS_OFF);
    float* sb0 = (float*)(smem + SB_OFF);
    float* sb1 = (float*)(smem + SB_OFF + 128);
    const uint32_t sbase = s2u(smem);

    const int tid = threadIdx.x;
    const int wid = tid >> 5, lid = tid & 31;
    const int cta = blockIdx.x;
    const int g = lid >> 2, q = lid & 3;
    const int R = wid * 16;
    const int xr = q << 2;   // fragment swizzle

    unsigned bbase = *(volatile unsigned*)&g_bargen;
    unsigned nbar = 0;

    if (tid == 0) {
        for (int s = 0; s < NSTG; s++) {
            mbar_init(sbase + FULL_MB(s), 1);
            mbar_init(sbase + EMPTY_MB(s), 8);
        }
    }
    if (tid < 32) {
        int gc = (tid >> 3) * HH + cta * 8 + (tid & 7);
        sb0[tid] = b0g[gc];
        sb1[tid] = b1g[gc];
    }
    {
        uint2 z2 = make_uint2(0u, 0u);
        uint2* z0 = &g_h0[0][0][0];
        uint2* z1 = &g_h1[0][0][0];
        for (int i = cta * NTHR + tid; i < 512 * BB; i += NCTA * NTHR) { z0[i] = z2; z1[i] = z2; }
    }

    const int m  = tid >> 1;
    const int uh = (tid & 1) * 4;
    float cs0[4] = {0.f, 0.f, 0.f, 0.f};
    float cs1[4] = {0.f, 0.f, 0.f, 0.f};
    const int mylen = il[m];

    int pstg = 0, pph = 1;
    int cstg = 0, cph = 0;

    grid_sync(bbase, ++nbar);

    for (int t = 0; t < TT; t++) {
        const int pr = t & 1, pw = pr ^ 1;
        for (int layer = 0; layer < 2; layer++) {
            const int nc = layer ? 32 : 20;

            auto issue = [&](int c) {
                mwait(sbase + EMPTY_MB(pstg), (unsigned)pph);
                mexpect(sbase + FULL_MB(pstg), 40960u);
                const uint2* ap;
                const uint2* bp_;
                if (layer == 0) {
                    ap  = (c < 4) ? &g_x[t][c * 32][0] : &g_h0[pr][c * 32 - 128][0];
                    bp_ = &g_w0[c][cta][0][0];
                } else {
                    ap  = (c < 16) ? &g_h0[pw][c * 32][0] : &g_h1[pr][(c - 16) * 32][0];
                    bp_ = &g_w1[c][cta][0][0];
                }
                bulk(sbase + pstg * 40960, ap, 32768u, sbase + FULL_MB(pstg));
                bulk(sbase + pstg * 40960 + 32768, bp_, 8192u, sbase + FULL_MB(pstg));
                if (++pstg == NSTG) { pstg = 0; pph ^= 1; }
            };

            float C[4][4];
#pragma unroll
            for (int a = 0; a < 4; a++)
#pragma unroll
                for (int d = 0; d < 4; d++) C[a][d] = 0.f;

            if (tid == 0) {
                for (int i = 0; i < NSTG - 1 && i < nc; i++) issue(i);
            }

            for (int ch = 0; ch < nc; ch++) {
                if (tid == 0 && ch + NSTG - 1 < nc) issue(ch + NSTG - 1);

                mwait(sbase + FULL_MB(cstg), (unsigned)cph);
                const uint2* Ab = (const uint2*)(smem + cstg * 40960);
                const uint2* Bb = (const uint2*)(smem + cstg * 40960 + 32768);
#pragma unroll
                for (int s = 0; s < 4; s++) {
                    uint2 a0 = Ab[(s * 8 + q) * 128 + ((R + g) ^ xr)];
                    uint2 a1 = Ab[(s * 8 + q) * 128 + ((R + g + 8) ^ xr)];
                    uint2 a2 = Ab[(s * 8 + q + 4) * 128 + ((R + g) ^ xr)];
                    uint2 a3 = Ab[(s * 8 + q + 4) * 128 + ((R + g + 8) ^ xr)];
#pragma unroll
                    for (int nt = 0; nt < 4; nt++) {
                        uint2 B0 = Bb[(s * 8 + q) * 32 + ((nt * 8 + g) ^ xr)];
                        uint2 B1 = Bb[(s * 8 + q + 4) * 32 + ((nt * 8 + g) ^ xr)];
                        bmma(C[nt], a0.x, a1.x, a2.x, a3.x, B0.x, B1.x);
                        bmma(C[nt], a0.y, a1.y, a2.y, a3.y, B0.x, B1.x);
                        bmma(C[nt], a0.x, a1.x, a2.x, a3.x, B0.y, B1.y);
                    }
                }
                __syncwarp();
                if (lid == 0) marrive(sbase + EMPTY_MB(cstg));
                if (++cstg == NSTG) { cstg = 0; cph ^= 1; }
            }

            // epilogue: C -> Zs
#pragma unroll
            for (int nt = 0; nt < 4; nt++) {
                const int col = nt * 8 + 2 * q;
                *(float2*)&Zs[(R + g) * 36 + col]     = make_float2(C[nt][0], C[nt][1]);
                *(float2*)&Zs[(R + g + 8) * 36 + col] = make_float2(C[nt][2], C[nt][3]);
            }
            __syncthreads();

            // cell: all 256 threads, 4 units each
            {
                const float* sb = layer ? sb1 : sb0;
                float* cs = layer ? cs1 : cs0;
                float4 vi = *(float4*)&Zs[m * 36 + 0 + uh];
                float4 vj = *(float4*)&Zs[m * 36 + 8 + uh];
                float4 vf = *(float4*)&Zs[m * 36 + 16 + uh];
                float4 vo = *(float4*)&Zs[m * 36 + 24 + uh];
                float ziv[4] = {vi.x, vi.y, vi.z, vi.w};
                float zjv[4] = {vj.x, vj.y, vj.z, vj.w};
                float zfv[4] = {vf.x, vf.y, vf.z, vf.w};
                float zov[4] = {vo.x, vo.y, vo.z, vo.w};
                float nh[4];
#pragma unroll
                for (int j = 0; j < 4; j++) {
                    float zi = ziv[j] + sb[uh + j];
                    float zj = zjv[j] + sb[8 + uh + j];
                    float zf = zfv[j] + sb[16 + uh + j];
                    float zo = zov[j] + sb[24 + uh + j];
                    float nc = cs[j] * sigf(zf + 1.0f) + sigf(zi) * tanhf(zj);
                    nh[j] = tanhf(nc) * sigf(zo);
                    cs[j] = nc;
                }
                uint2 p0 = pack_pair(nh[0], nh[1]);
                uint2 p1 = pack_pair(nh[2], nh[3]);
                const int pg = cta * 4 + (tid & 1) * 2;
                const int m0 = m ^ ((pg & 3) << 2);
                const int m1 = m ^ (((pg + 1) & 3) << 2);
                if (layer == 0) {
                    g_h0[pw][pg][m0] = p0;
                    g_h0[pw][pg + 1][m1] = p1;
                } else {
                    g_h1[pw][pg][m0] = p0;
                    g_h1[pw][pg + 1][m1] = p1;
                    if (t == mylen - 1)
                        *(float4*)&out[m * HH + cta * 8 + uh] =
                            make_float4(nh[0], nh[1], nh[2], nh[3]);
                }
            }
            grid_sync(bbase, ++nbar);
        }
    }
}

extern "C" void kernel_launch(void* const* d_in, const int* in_sizes, int n_in,
                              void* d_out, int out_size) {
    const int*   input_batch   = (const int*)d_in[0];
    const int*   input_lengths = (const int*)d_in[1];
    const float* emb           = (const float*)d_in[2];
    const float* W0            = (const float*)d_in[3];
    const float* b0            = (const float*)d_in[4];
    const float* W1            = (const float*)d_in[5];
    const float* b1            = (const float*)d_in[6];
    float*       out           = (float*)d_out;

    cudaFuncSetAttribute(lstm_main, cudaFuncAttributeMaxDynamicSharedMemorySize, SMEM_DYN);
    prep_x<<<1024, 256>>>(input_batch, emb);
    prep_w<<<2048, 256>>>(W0, W1);
    lstm_main<<<NCTA, NTHR, SMEM_DYN>>>(input_lengths, b0, b1, out);
}

// round 8
// speedup vs baseline: 4.2664x; 1.0448x over previous
#include <cuda_runtime.h>
#include <math.h>
#include <stdint.h>

#define BB 128
#define TT 512
#define HH 1024
#define NCTA 128
#define NTHR 256
#define NSTG 4

// smem: stage s: A 32KB @ s*40960, B 8KB @ s*40960+32768
//       Zs float[128][36] @163840; sb @182272; mbars @182784
#define ZS_OFF   163840
#define SB_OFF   182272
#define MB_OFF   182784
#define FULL_MB(s)  (MB_OFF + (s) * 16)
#define EMPTY_MB(s) (MB_OFF + (s) * 16 + 8)
#define SMEM_DYN 183296

// ---- persistent device state: packed (bf16-hi, bf16-lo) pairs ----
// A images swizzled: [p][m] stored at row m ^ ((p&3)<<2)
// B images swizzled: [ch][cb][p][c] stored at col c ^ ((p&3)<<2)
__device__ __align__(16) uint2 g_x [TT][128][BB];
__device__ __align__(16) uint2 g_h0[2][512][BB];
__device__ __align__(16) uint2 g_h1[2][512][BB];
__device__ __align__(16) uint2 g_w0[20][128][32][32];
__device__ __align__(16) uint2 g_w1[32][128][32][32];
__device__ unsigned g_barcnt, g_bargen;

__device__ __forceinline__ float sigf(float x) { return 1.0f / (1.0f + expf(-x)); }

__device__ __forceinline__ uint32_t s2u(const void* p) {
    uint32_t a;
    asm("{ .reg .u64 t; cvta.to.shared.u64 t, %1; cvt.u32.u64 %0, t; }" : "=r"(a) : "l"(p));
    return a;
}
__device__ __forceinline__ uint2 pack_pair(float e0, float e1) {
    uint32_t hi, lo;
    asm("cvt.rn.bf16x2.f32 %0, %1, %2;" : "=r"(hi) : "f"(e1), "f"(e0));
    float r0 = e0 - __uint_as_float(hi << 16);
    float r1 = e1 - __uint_as_float(hi & 0xFFFF0000u);
    asm("cvt.rn.bf16x2.f32 %0, %1, %2;" : "=r"(lo) : "f"(r1), "f"(r0));
    return make_uint2(hi, lo);
}
__device__ __forceinline__ void bmma(float* c, uint32_t a0, uint32_t a1, uint32_t a2,
                                     uint32_t a3, uint32_t b0, uint32_t b1) {
    asm("mma.sync.aligned.m16n8k16.row.col.f32.bf16.bf16.f32 "
        "{%0,%1,%2,%3},{%4,%5,%6,%7},{%8,%9},{%0,%1,%2,%3};"
        : "+f"(c[0]), "+f"(c[1]), "+f"(c[2]), "+f"(c[3])
        : "r"(a0), "r"(a1), "r"(a2), "r"(a3), "r"(b0), "r"(b1));
}
__device__ __forceinline__ void mbar_init(uint32_t b, uint32_t n) {
    asm volatile("mbarrier.init.shared.b64 [%0], %1;" :: "r"(b), "r"(n) : "memory");
}
__device__ __forceinline__ void mexpect(uint32_t b, uint32_t tx) {
    asm volatile("mbarrier.arrive.expect_tx.shared.b64 _, [%0], %1;" :: "r"(b), "r"(tx) : "memory");
}
__device__ __forceinline__ void marrive(uint32_t b) {
    asm volatile("mbarrier.arrive.shared.b64 _, [%0];" :: "r"(b) : "memory");
}
__device__ __forceinline__ void mwait(uint32_t b, uint32_t ph) {
    asm volatile(
        "{\n\t.reg .pred P;\n"
        "W_%=:\n\t"
        "mbarrier.try_wait.parity.acquire.cta.shared::cta.b64 P, [%0], %1, 0x989680;\n\t"
        "@P bra D_%=;\n\t"
        "bra W_%=;\n"
        "D_%=:\n\t}"
        :: "r"(b), "r"(ph) : "memory");
}
__device__ __forceinline__ void bulk(uint32_t dst, const void* src, uint32_t bytes, uint32_t mbar) {
    asm volatile("cp.async.bulk.shared::cluster.global.mbarrier::complete_tx::bytes [%0], [%1], %2, [%3];"
        :: "r"(dst), "l"(src), "r"(bytes), "r"(mbar) : "memory");
}
__device__ __forceinline__ void grid_sync(unsigned base, unsigned nbar) {
    __syncthreads();
    if (threadIdx.x == 0) {
        __threadfence();
        unsigned old = atomicAdd(&g_barcnt, 1u);
        if (old == gridDim.x - 1) {
            g_barcnt = 0;
            __threadfence();
            atomicAdd(&g_bargen, 1u);
        } else {
            while ((*(volatile unsigned*)&g_bargen) - base < nbar) { __nanosleep(64); }
            __threadfence();
        }
    }
    __syncthreads();
}

// ---- prep: embeddings -> g_x (A-swizzled) ----
__global__ void prep_x(const int* __restrict__ ib, const float* __restrict__ emb) {
    const int N = TT * 128 * BB;
    for (int i = blockIdx.x * blockDim.x + threadIdx.x; i < N;
         i += gridDim.x * blockDim.x) {
        int m = i & 127;
        int p = (i >> 7) & 127;
        int t = i >> 14;
        const float* s = emb + (size_t)ib[m * TT + t] * 256 + 2 * p;
        g_x[t][p][m ^ ((p & 3) << 2)] = pack_pair(s[0], s[1]);
    }
}

// ---- prep: W -> packed [chunk][cb][p][c'] (B-swizzled) ----
__global__ void prep_w(const float* __restrict__ W0, const float* __restrict__ W1) {
    const long n0 = 20L * 131072, n1 = 32L * 131072;
    for (long i = (long)blockIdx.x * blockDim.x + threadIdx.x; i < n0 + n1;
         i += (long)gridDim.x * blockDim.x) {
        long j = i;
        const float* W = W0;
        uint2* dst = &g_w0[0][0][0][0];
        if (j >= n0) { j -= n0; W = W1; dst = &g_w1[0][0][0][0]; }
        int c  = (int)(j & 31);
        int p  = (int)((j >> 5) & 31);
        int cb = (int)((j >> 10) & 127);
        int ch = (int)(j >> 17);
        int gcol = ((c >> 3) & 3) * HH + cb * 8 + (c & 7);
        int k0 = 2 * (ch * 32 + p);
        dst[(j & ~31L) | (long)(c ^ ((p & 3) << 2))] =
            pack_pair(W[(size_t)k0 * 4096 + gcol],
                      W[(size_t)(k0 + 1) * 4096 + gcol]);
    }
}

__global__ void __launch_bounds__(NTHR, 1)
lstm_main(const int* __restrict__ il,
          const float* __restrict__ b0g,
          const float* __restrict__ b1g,
          float* __restrict__ out) {
    extern __shared__ char smem[];
    float* Zs  = (float*)(smem + ZS_OFF);
    float* sb0 = (float*)(smem + SB_OFF);
    float* sb1 = (float*)(smem + SB_OFF + 128);
    const uint32_t sbase = s2u(smem);

    const int tid = threadIdx.x;
    const int wid = tid >> 5, lid = tid & 31;
    const int cta = blockIdx.x;
    const int g = lid >> 2, q = lid & 3;
    const int mt = wid >> 1;          // m-tile of 32 rows
    const int kh = wid & 1;           // K-half of the chunk
    const int R = mt * 32;
    const int xr = q << 2;            // fragment swizzle

    unsigned bbase = *(volatile unsigned*)&g_bargen;
    unsigned nbar = 0;

    if (tid == 0) {
        for (int s = 0; s < NSTG; s++) {
            mbar_init(sbase + FULL_MB(s), 1);
            mbar_init(sbase + EMPTY_MB(s), 8);
        }
    }
    if (tid < 32) {
        int gc = (tid >> 3) * HH + cta * 8 + (tid & 7);
        sb0[tid] = b0g[gc];
        sb1[tid] = b1g[gc];
    }
    {
        uint2 z2 = make_uint2(0u, 0u);
        uint2* z0 = &g_h0[0][0][0];
        uint2* z1 = &g_h1[0][0][0];
        for (int i = cta * NTHR + tid; i < 512 * BB; i += NCTA * NTHR) { z0[i] = z2; z1[i] = z2; }
    }

    const int m  = tid >> 1;
    const int uh = (tid & 1) * 4;
    float cs0[4] = {0.f, 0.f, 0.f, 0.f};
    float cs1[4] = {0.f, 0.f, 0.f, 0.f};
    const int mylen = il[m];

    int pstg = 0, pph = 1;
    int cstg = 0, cph = 0;

    grid_sync(bbase, ++nbar);

    for (int t = 0; t < TT; t++) {
        const int pr = t & 1, pw = pr ^ 1;
        for (int layer = 0; layer < 2; layer++) {
            const int nc = layer ? 32 : 20;

            auto issue = [&](int c) {
                mwait(sbase + EMPTY_MB(pstg), (unsigned)pph);
                mexpect(sbase + FULL_MB(pstg), 40960u);
                const uint2* ap;
                const uint2* bp_;
                if (layer == 0) {
                    ap  = (c < 4) ? &g_x[t][c * 32][0] : &g_h0[pr][c * 32 - 128][0];
                    bp_ = &g_w0[c][cta][0][0];
                } else {
                    ap  = (c < 16) ? &g_h0[pw][c * 32][0] : &g_h1[pr][(c - 16) * 32][0];
                    bp_ = &g_w1[c][cta][0][0];
                }
                bulk(sbase + pstg * 40960, ap, 32768u, sbase + FULL_MB(pstg));
                bulk(sbase + pstg * 40960 + 32768, bp_, 8192u, sbase + FULL_MB(pstg));
                if (++pstg == NSTG) { pstg = 0; pph ^= 1; }
            };

            float C[2][4][4];
#pragma unroll
            for (int a = 0; a < 2; a++)
#pragma unroll
                for (int b = 0; b < 4; b++)
#pragma unroll
                    for (int d = 0; d < 4; d++) C[a][b][d] = 0.f;

            if (tid == 0) {
                for (int i = 0; i < NSTG - 1 && i < nc; i++) issue(i);
            }

            for (int ch = 0; ch < nc; ch++) {
                if (tid == 0 && ch + NSTG - 1 < nc) issue(ch + NSTG - 1);

                mwait(sbase + FULL_MB(cstg), (unsigned)cph);
                const uint2* Ab = (const uint2*)(smem + cstg * 40960);
                const uint2* Bb = (const uint2*)(smem + cstg * 40960 + 32768);

                // load all fragments for this warp's K-half up front
                uint2 Af[2][2][4];
                uint2 Bf[2][4][2];
#pragma unroll
                for (int sl = 0; sl < 2; sl++) {
                    const int s  = kh * 2 + sl;
                    const int pa = (s * 8 + q) * 128;
                    const int pb = (s * 8 + q + 4) * 128;
#pragma unroll
                    for (int rt = 0; rt < 2; rt++) {
                        const int r0 = (R + rt * 16 + g) ^ xr;
                        const int r1 = (R + rt * 16 + g + 8) ^ xr;
                        Af[sl][rt][0] = Ab[pa + r0];
                        Af[sl][rt][1] = Ab[pa + r1];
                        Af[sl][rt][2] = Ab[pb + r0];
                        Af[sl][rt][3] = Ab[pb + r1];
                    }
                    const int ba = (s * 8 + q) * 32;
                    const int bb2 = (s * 8 + q + 4) * 32;
#pragma unroll
                    for (int nt = 0; nt < 4; nt++) {
                        const int cc = (nt * 8 + g) ^ xr;
                        Bf[sl][nt][0] = Bb[ba + cc];
                        Bf[sl][nt][1] = Bb[bb2 + cc];
                    }
                }
#pragma unroll
                for (int sl = 0; sl < 2; sl++)
#pragma unroll
                    for (int rt = 0; rt < 2; rt++)
#pragma unroll
                        for (int nt = 0; nt < 4; nt++) {
                            bmma(C[rt][nt], Af[sl][rt][0].x, Af[sl][rt][1].x,
                                 Af[sl][rt][2].x, Af[sl][rt][3].x,
                                 Bf[sl][nt][0].x, Bf[sl][nt][1].x);
                            bmma(C[rt][nt], Af[sl][rt][0].y, Af[sl][rt][1].y,
                                 Af[sl][rt][2].y, Af[sl][rt][3].y,
                                 Bf[sl][nt][0].x, Bf[sl][nt][1].x);
                            bmma(C[rt][nt], Af[sl][rt][0].x, Af[sl][rt][1].x,
                                 Af[sl][rt][2].x, Af[sl][rt][3].x,
                                 Bf[sl][nt][0].y, Bf[sl][nt][1].y);
                        }
                __syncwarp();
                if (lid == 0) marrive(sbase + EMPTY_MB(cstg));
                if (++cstg == NSTG) { cstg = 0; cph ^= 1; }
            }

            // epilogue: K-half reduce into Zs
            if (kh == 0) {
#pragma unroll
                for (int rt = 0; rt < 2; rt++)
#pragma unroll
                    for (int nt = 0; nt < 4; nt++) {
                        const int col = nt * 8 + 2 * q;
                        *(float2*)&Zs[(R + rt * 16 + g) * 36 + col] =
                            make_float2(C[rt][nt][0], C[rt][nt][1]);
                        *(float2*)&Zs[(R + rt * 16 + g + 8) * 36 + col] =
                            make_float2(C[rt][nt][2], C[rt][nt][3]);
                    }
            }
            __syncthreads();
            if (kh == 1) {
#pragma unroll
                for (int rt = 0; rt < 2; rt++)
#pragma unroll
                    for (int nt = 0; nt < 4; nt++) {
                        const int col = nt * 8 + 2 * q;
                        float2 v0 = *(float2*)&Zs[(R + rt * 16 + g) * 36 + col];
                        float2 v1 = *(float2*)&Zs[(R + rt * 16 + g + 8) * 36 + col];
                        v0.x += C[rt][nt][0]; v0.y += C[rt][nt][1];
                        v1.x += C[rt][nt][2]; v1.y += C[rt][nt][3];
                        *(float2*)&Zs[(R + rt * 16 + g) * 36 + col] = v0;
                        *(float2*)&Zs[(R + rt * 16 + g + 8) * 36 + col] = v1;
                    }
            }
            __syncthreads();

            // cell: all 256 threads, 4 units each
            {
                const float* sb = layer ? sb1 : sb0;
                float* cs = layer ? cs1 : cs0;
                float4 vi = *(float4*)&Zs[m * 36 + 0 + uh];
                float4 vj = *(float4*)&Zs[m * 36 + 8 + uh];
                float4 vf = *(float4*)&Zs[m * 36 + 16 + uh];
                float4 vo = *(float4*)&Zs[m * 36 + 24 + uh];
                float ziv[4] = {vi.x, vi.y, vi.z, vi.w};
                float zjv[4] = {vj.x, vj.y, vj.z, vj.w};
                float zfv[4] = {vf.x, vf.y, vf.z, vf.w};
                float zov[4] = {vo.x, vo.y, vo.z, vo.w};
                float nh[4];
#pragma unroll
                for (int j = 0; j < 4; j++) {
                    float zi = ziv[j] + sb[uh + j];
                    float zj = zjv[j] + sb[8 + uh + j];
                    float zf = zfv[j] + sb[16 + uh + j];
                    float zo = zov[j] + sb[24 + uh + j];
                    float nc = cs[j] * sigf(zf + 1.0f) + sigf(zi) * tanhf(zj);
                    nh[j] = tanhf(nc) * sigf(zo);
                    cs[j] = nc;
                }
                uint2 p0 = pack_pair(nh[0], nh[1]);
                uint2 p1 = pack_pair(nh[2], nh[3]);
                const int pg = cta * 4 + (tid & 1) * 2;
                const int m0 = m ^ ((pg & 3) << 2);
                const int m1 = m ^ (((pg + 1) & 3) << 2);
                if (layer == 0) {
                    g_h0[pw][pg][m0] = p0;
                    g_h0[pw][pg + 1][m1] = p1;
                } else {
                    g_h1[pw][pg][m0] = p0;
                    g_h1[pw][pg + 1][m1] = p1;
                    if (t == mylen - 1)
                        *(float4*)&out[m * HH + cta * 8 + uh] =
                            make_float4(nh[0], nh[1], nh[2], nh[3]);
                }
            }
            grid_sync(bbase, ++nbar);
        }
    }
}

extern "C" void kernel_launch(void* const* d_in, const int* in_sizes, int n_in,
                              void* d_out, int out_size) {
    const int*   input_batch   = (const int*)d_in[0];
    const int*   input_lengths = (const int*)d_in[1];
    const float* emb           = (const float*)d_in[2];
    const float* W0            = (const float*)d_in[3];
    const float* b0            = (const float*)d_in[4];
    const float* W1            = (const float*)d_in[5];
    const float* b1            = (const float*)d_in[6];
    float*       out           = (float*)d_out;

    cudaFuncSetAttribute(lstm_main, cudaFuncAttributeMaxDynamicSharedMemorySize, SMEM_DYN);
    prep_x<<<1024, 256>>>(input_batch, emb);
    prep_w<<<2048, 256>>>(W0, W1);
    lstm_main<<<NCTA, NTHR, SMEM_DYN>>>(input_lengths, b0, b1, out);
}

// round 10
// speedup vs baseline: 5.0152x; 1.1755x over previous
#include <cuda_runtime.h>
#include <math.h>
#include <stdint.h>

#define BB 128
#define TT 512
#define HH 1024
#define NCTA 128
#define NTHR 288
#define NSTG 5

// smem: stage s<5: A 32KB @ s*40960, B 8KB @ s*40960+32768
//       Zs float[128][36] @204800; sb @223232; mbars @223744
#define ZS_OFF   204800
#define SB_OFF   223232
#define MB_OFF   223744
#define FULL_MB(s)  (MB_OFF + (s) * 16)
#define EMPTY_MB(s) (MB_OFF + (s) * 16 + 8)
#define SMEM_DYN 223872

// ---- persistent device state: packed (bf16-hi, bf16-lo) pairs ----
// A images swizzled: [p][m] stored at row m ^ ((p&3)<<2)
// B images swizzled: [ch][cb][p][c] stored at col c ^ ((p&3)<<2)
__device__ __align__(16) uint2 g_x [TT][128][BB];
__device__ __align__(16) uint2 g_h0[2][512][BB];
__device__ __align__(16) uint2 g_h1[2][512][BB];
__device__ __align__(16) uint2 g_w0[20][128][32][32];
__device__ __align__(16) uint2 g_w1[32][128][32][32];
__device__ unsigned g_barcnt, g_bargen;

__device__ __forceinline__ float sigf(float x) { return 1.0f / (1.0f + expf(-x)); }

__device__ __forceinline__ uint32_t s2u(const void* p) {
    uint32_t a;
    asm("{ .reg .u64 t; cvta.to.shared.u64 t, %1; cvt.u32.u64 %0, t; }" : "=r"(a) : "l"(p));
    return a;
}
__device__ __forceinline__ uint2 pack_pair(float e0, float e1) {
    uint32_t hi, lo;
    asm("cvt.rn.bf16x2.f32 %0, %1, %2;" : "=r"(hi) : "f"(e1), "f"(e0));
    float r0 = e0 - __uint_as_float(hi << 16);
    float r1 = e1 - __uint_as_float(hi & 0xFFFF0000u);
    asm("cvt.rn.bf16x2.f32 %0, %1, %2;" : "=r"(lo) : "f"(r1), "f"(r0));
    return make_uint2(hi, lo);
}
__device__ __forceinline__ void bmma(float* c, uint32_t a0, uint32_t a1, uint32_t a2,
                                     uint32_t a3, uint32_t b0, uint32_t b1) {
    asm("mma.sync.aligned.m16n8k16.row.col.f32.bf16.bf16.f32 "
        "{%0,%1,%2,%3},{%4,%5,%6,%7},{%8,%9},{%0,%1,%2,%3};"
        : "+f"(c[0]), "+f"(c[1]), "+f"(c[2]), "+f"(c[3])
        : "r"(a0), "r"(a1), "r"(a2), "r"(a3), "r"(b0), "r"(b1));
}
__device__ __forceinline__ void mbar_init(uint32_t b, uint32_t n) {
    asm volatile("mbarrier.init.shared.b64 [%0], %1;" :: "r"(b), "r"(n) : "memory");
}
__device__ __forceinline__ void mexpect(uint32_t b, uint32_t tx) {
    asm volatile("mbarrier.arrive.expect_tx.shared.b64 _, [%0], %1;" :: "r"(b), "r"(tx) : "memory");
}
__device__ __forceinline__ void marrive(uint32_t b) {
    asm volatile("mbarrier.arrive.shared.b64 _, [%0];" :: "r"(b) : "memory");
}
__device__ __forceinline__ void mwait(uint32_t b, uint32_t ph) {
    asm volatile(
        "{\n\t.reg .pred P;\n"
        "W_%=:\n\t"
        "mbarrier.try_wait.parity.acquire.cta.shared::cta.b64 P, [%0], %1, 0x989680;\n\t"
        "@P bra D_%=;\n\t"
        "bra W_%=;\n"
        "D_%=:\n\t}"
        :: "r"(b), "r"(ph) : "memory");
}
__device__ __forceinline__ void bulk(uint32_t dst, const void* src, uint32_t bytes, uint32_t mbar) {
    asm volatile("cp.async.bulk.shared::cluster.global.mbarrier::complete_tx::bytes [%0], [%1], %2, [%3];"
        :: "r"(dst), "l"(src), "r"(bytes), "r"(mbar) : "memory");
}
__device__ __forceinline__ void grid_sync(unsigned base, unsigned nbar) {
    __syncthreads();
    if (threadIdx.x == 0) {
        __threadfence();
        unsigned old = atomicAdd(&g_barcnt, 1u);
        if (old == gridDim.x - 1) {
            g_barcnt = 0;
            __threadfence();
            atomicAdd(&g_bargen, 1u);
        } else {
            while ((*(volatile unsigned*)&g_bargen) - base < nbar) { __nanosleep(64); }
            __threadfence();
        }
    }
    __syncthreads();
}

// ---- prep: embeddings -> g_x (A-swizzled) ----
__global__ void prep_x(const int* __restrict__ ib, const float* __restrict__ emb) {
    const int N = TT * 128 * BB;
    for (int i = blockIdx.x * blockDim.x + threadIdx.x; i < N;
         i += gridDim.x * blockDim.x) {
        int m = i & 127;
        int p = (i >> 7) & 127;
        int t = i >> 14;
        const float* s = emb + (size_t)ib[m * TT + t] * 256 + 2 * p;
        g_x[t][p][m ^ ((p & 3) << 2)] = pack_pair(s[0], s[1]);
    }
}

// ---- prep: W -> packed [chunk][cb][p][c'] (B-swizzled) ----
__global__ void prep_w(const float* __restrict__ W0, const float* __restrict__ W1) {
    const long n0 = 20L * 131072, n1 = 32L * 131072;
    for (long i = (long)blockIdx.x * blockDim.x + threadIdx.x; i < n0 + n1;
         i += (long)gridDim.x * blockDim.x) {
        long j = i;
        const float* W = W0;
        uint2* dst = &g_w0[0][0][0][0];
        if (j >= n0) { j -= n0; W = W1; dst = &g_w1[0][0][0][0]; }
        int c  = (int)(j & 31);
        int p  = (int)((j >> 5) & 31);
        int cb = (int)((j >> 10) & 127);
        int ch = (int)(j >> 17);
        int gcol = ((c >> 3) & 3) * HH + cb * 8 + (c & 7);
        int k0 = 2 * (ch * 32 + p);
        dst[(j & ~31L) | (long)(c ^ ((p & 3) << 2))] =
            pack_pair(W[(size_t)k0 * 4096 + gcol],
                      W[(size_t)(k0 + 1) * 4096 + gcol]);
    }
}

__global__ void __launch_bounds__(NTHR, 1)
lstm_main(const int* __restrict__ il,
          const float* __restrict__ b0g,
          const float* __restrict__ b1g,
          float* __restrict__ out) {
    extern __shared__ char smem[];
    float* Zs  = (float*)(smem + ZS_OFF);
    float* sb0 = (float*)(smem + SB_OFF);
    float* sb1 = (float*)(smem + SB_OFF + 128);
    const uint32_t sbase = s2u(smem);

    const int tid = threadIdx.x;
    const int wid = tid >> 5, lid = tid & 31;
    const int cta = blockIdx.x;
    const int g = lid >> 2, q = lid & 3;
    const int mt = wid >> 1;          // m-tile of 32 rows (compute warps)
    const int kh = wid & 1;           // K-half of the chunk
    const int R = mt * 32;
    const int xr = q << 2;            // fragment swizzle

    unsigned bbase = *(volatile unsigned*)&g_bargen;
    unsigned nbar = 0;

    if (tid == 0) {
        for (int s = 0; s < NSTG; s++) {
            mbar_init(sbase + FULL_MB(s), 1);
            mbar_init(sbase + EMPTY_MB(s), 8);
        }
    }
    if (tid < 32) {
        int gc = (tid >> 3) * HH + cta * 8 + (tid & 7);
        sb0[tid] = b0g[gc];
        sb1[tid] = b1g[gc];
    }
    {
        uint2 z2 = make_uint2(0u, 0u);
        uint2* z0 = &g_h0[0][0][0];
        uint2* z1 = &g_h1[0][0][0];
        for (int i = cta * NTHR + tid; i < 512 * BB; i += NCTA * NTHR) { z0[i] = z2; z1[i] = z2; }
    }

    const int m  = tid >> 1;          // cell row (valid tid < 256)
    const int uh = (tid & 1) * 4;
    float cs0[4] = {0.f, 0.f, 0.f, 0.f};
    float cs1[4] = {0.f, 0.f, 0.f, 0.f};
    const int mylen = (tid < 256) ? il[m] : 0;

    int pstg = 0, pph = 1;   // producer ring (warp 8 lane 0)
    int cstg = 0, cph = 0;   // consumer ring (compute warps)

    grid_sync(bbase, ++nbar);

    for (int t = 0; t < TT; t++) {
        const int pr = t & 1, pw = pr ^ 1;
        for (int layer = 0; layer < 2; layer++) {
            const int nc = layer ? 32 : 20;

            float C[2][4][4];
#pragma unroll
            for (int a = 0; a < 2; a++)
#pragma unroll
                for (int b = 0; b < 4; b++)
#pragma unroll
                    for (int d = 0; d < 4; d++) C[a][b][d] = 0.f;

            if (wid == 8) {
                // ---------------- dedicated producer warp ----------------
                if (lid == 0) {
                    for (int c = 0; c < nc; c++) {
                        mwait(sbase + EMPTY_MB(pstg), (unsigned)pph);
                        mexpect(sbase + FULL_MB(pstg), 40960u);
                        const uint2* ap;
                        const uint2* bp_;
                        if (layer == 0) {
                            ap  = (c < 4) ? &g_x[t][c * 32][0] : &g_h0[pr][c * 32 - 128][0];
                            bp_ = &g_w0[c][cta][0][0];
                        } else {
                            ap  = (c < 16) ? &g_h0[pw][c * 32][0] : &g_h1[pr][(c - 16) * 32][0];
                            bp_ = &g_w1[c][cta][0][0];
                        }
                        bulk(sbase + pstg * 40960, ap, 32768u, sbase + FULL_MB(pstg));
                        bulk(sbase + pstg * 40960 + 32768, bp_, 8192u, sbase + FULL_MB(pstg));
                        if (++pstg == NSTG) { pstg = 0; pph ^= 1; }
                    }
                }
            } else {
                // ---------------- compute warps 0..7 ----------------
                for (int ch = 0; ch < nc; ch++) {
                    mwait(sbase + FULL_MB(cstg), (unsigned)cph);
                    const uint2* Ab = (const uint2*)(smem + cstg * 40960);
                    const uint2* Bb = (const uint2*)(smem + cstg * 40960 + 32768);

                    uint2 Af[2][2][4];
                    uint2 Bf[2][4][2];
#pragma unroll
                    for (int sl = 0; sl < 2; sl++) {
                        const int s  = kh * 2 + sl;
                        const int pa = (s * 8 + q) * 128;
                        const int pb = (s * 8 + q + 4) * 128;
#pragma unroll
                        for (int rt = 0; rt < 2; rt++) {
                            const int r0 = (R + rt * 16 + g) ^ xr;
                            const int r1 = (R + rt * 16 + g + 8) ^ xr;
                            Af[sl][rt][0] = Ab[pa + r0];
                            Af[sl][rt][1] = Ab[pa + r1];
                            Af[sl][rt][2] = Ab[pb + r0];
                            Af[sl][rt][3] = Ab[pb + r1];
                        }
                        const int ba  = (s * 8 + q) * 32;
                        const int bb2 = (s * 8 + q + 4) * 32;
#pragma unroll
                        for (int nt = 0; nt < 4; nt++) {
                            const int cc = (nt * 8 + g) ^ xr;
                            Bf[sl][nt][0] = Bb[ba + cc];
                            Bf[sl][nt][1] = Bb[bb2 + cc];
                        }
                    }
#pragma unroll
                    for (int sl = 0; sl < 2; sl++)
#pragma unroll
                        for (int rt = 0; rt < 2; rt++)
#pragma unroll
                            for (int nt = 0; nt < 4; nt++) {
                                bmma(C[rt][nt], Af[sl][rt][0].x, Af[sl][rt][1].x,
                                     Af[sl][rt][2].x, Af[sl][rt][3].x,
                                     Bf[sl][nt][0].x, Bf[sl][nt][1].x);
                                bmma(C[rt][nt], Af[sl][rt][0].y, Af[sl][rt][1].y,
                                     Af[sl][rt][2].y, Af[sl][rt][3].y,
                                     Bf[sl][nt][0].x, Bf[sl][nt][1].x);
                                bmma(C[rt][nt], Af[sl][rt][0].x, Af[sl][rt][1].x,
                                     Af[sl][rt][2].x, Af[sl][rt][3].x,
                                     Bf[sl][nt][0].y, Bf[sl][nt][1].y);
                            }
                    __syncwarp();
                    if (lid == 0) marrive(sbase + EMPTY_MB(cstg));
                    if (++cstg == NSTG) { cstg = 0; cph ^= 1; }
                }

                // epilogue part 1: K-half 0 stores (before block-wide sync)
                if (kh == 0) {
#pragma unroll
                    for (int rt = 0; rt < 2; rt++)
#pragma unroll
                        for (int nt = 0; nt < 4; nt++) {
                            const int col = nt * 8 + 2 * q;
                            *(float2*)&Zs[(R + rt * 16 + g) * 36 + col] =
                                make_float2(C[rt][nt][0], C[rt][nt][1]);
                            *(float2*)&Zs[(R + rt * 16 + g + 8) * 36 + col] =
                                make_float2(C[rt][nt][2], C[rt][nt][3]);
                        }
                }
            }

            __syncthreads();   // all 9 warps: kh0 stores visible

            // epilogue part 2: K-half 1 accumulates
            if (wid < 8 && kh == 1) {
#pragma unroll
                for (int rt = 0; rt < 2; rt++)
#pragma unroll
                    for (int nt = 0; nt < 4; nt++) {
                        const int col = nt * 8 + 2 * q;
                        float2 v0 = *(float2*)&Zs[(R + rt * 16 + g) * 36 + col];
                        float2 v1 = *(float2*)&Zs[(R + rt * 16 + g + 8) * 36 + col];
                        v0.x += C[rt][nt][0]; v0.y += C[rt][nt][1];
                        v1.x += C[rt][nt][2]; v1.y += C[rt][nt][3];
                        *(float2*)&Zs[(R + rt * 16 + g) * 36 + col] = v0;
                        *(float2*)&Zs[(R + rt * 16 + g + 8) * 36 + col] = v1;
                    }
            }

            __syncthreads();   // all 9 warps: Z complete

            // cell: threads 0..255, 4 units each
            if (tid < 256) {
                const float* sb = layer ? sb1 : sb0;
                float* cs = layer ? cs1 : cs0;
                float4 vi = *(float4*)&Zs[m * 36 + 0 + uh];
                float4 vj = *(float4*)&Zs[m * 36 + 8 + uh];
                float4 vf = *(float4*)&Zs[m * 36 + 16 + uh];
                float4 vo = *(float4*)&Zs[m * 36 + 24 + uh];
                float ziv[4] = {vi.x, vi.y, vi.z, vi.w};
                float zjv[4] = {vj.x, vj.y, vj.z, vj.w};
                float zfv[4] = {vf.x, vf.y, vf.z, vf.w};
                float zov[4] = {vo.x, vo.y, vo.z, vo.w};
                float nh[4];
#pragma unroll
                for (int j = 0; j < 4; j++) {
                    float zi = ziv[j] + sb[uh + j];
                    float zj = zjv[j] + sb[8 + uh + j];
                    float zf = zfv[j] + sb[16 + uh + j];
                    float zo = zov[j] + sb[24 + uh + j];
                    float nc = cs[j] * sigf(zf + 1.0f) + sigf(zi) * tanhf(zj);
                    nh[j] = tanhf(nc) * sigf(zo);
                    cs[j] = nc;
                }
                uint2 p0 = pack_pair(nh[0], nh[1]);
                uint2 p1 = pack_pair(nh[2], nh[3]);
                const int pg = cta * 4 + (tid & 1) * 2;
                const int m0 = m ^ ((pg & 3) << 2);
                const int m1 = m ^ (((pg + 1) & 3) << 2);
                if (layer == 0) {
                    g_h0[pw][pg][m0] = p0;
                    g_h0[pw][pg + 1][m1] = p1;
                } else {
                    g_h1[pw][pg][m0] = p0;
                    g_h1[pw][pg + 1][m1] = p1;
                    if (t == mylen - 1)
                        *(float4*)&out[m * HH + cta * 8 + uh] =
                            make_float4(nh[0], nh[1], nh[2], nh[3]);
                }
            }

            if (layer == 0) {
                grid_sync(bbase, ++nbar);   // the one global sync per step
            } else {
                __syncthreads();            // intra-CTA: protect Zs reuse
            }
        }
    }
}

extern "C" void kernel_launch(void* const* d_in, const int* in_sizes, int n_in,
                              void* d_out, int out_size) {
    const int*   input_batch   = (const int*)d_in[0];
    const int*   input_lengths = (const int*)d_in[1];
    const float* emb           = (const float*)d_in[2];
    const float* W0            = (const float*)d_in[3];
    const float* b0            = (const float*)d_in[4];
    const float* W1            = (const float*)d_in[5];
    const float* b1            = (const float*)d_in[6];
    float*       out           = (float*)d_out;

    cudaFuncSetAttribute(lstm_main, cudaFuncAttributeMaxDynamicSharedMemorySize, SMEM_DYN);
    prep_x<<<1024, 256>>>(input_batch, emb);
    prep_w<<<2048, 256>>>(W0, W1);
    lstm_main<<<NCTA, NTHR, SMEM_DYN>>>(input_lengths, b0, b1, out);
}

// round 11
// speedup vs baseline: 5.2490x; 1.0466x over previous
#include <cuda_runtime.h>
#include <math.h>
#include <stdint.h>

#define BB 128
#define TT 512
#define HH 1024
#define NCTA 128
#define NTHR 288
#define NSTG 5

// smem: stage s<5: A 32KB @ s*40960, B 8KB @ s*40960+32768
//       Zs float[128][36] @204800; sb @223232; mbars @223744
#define ZS_OFF   204800
#define SB_OFF   223232
#define MB_OFF   223744
#define FULL_MB(s)  (MB_OFF + (s) * 16)
#define EMPTY_MB(s) (MB_OFF + (s) * 16 + 8)
#define SMEM_DYN 223872

// ---- persistent device state: packed (bf16-hi, bf16-lo) pairs ----
// A images swizzled: [p][m] stored at row m ^ ((p&3)<<2)
// B images swizzled: [ch][cb][p][c] stored at col c ^ ((p&3)<<2)
__device__ __align__(16) uint2 g_x [TT][128][BB];
__device__ __align__(16) uint2 g_h0[2][512][BB];
__device__ __align__(16) uint2 g_h1[2][512][BB];
__device__ __align__(16) uint2 g_w0[20][128][32][32];
__device__ __align__(16) uint2 g_w1[32][128][32][32];
// split grid-barrier counters: A = mid-step events, B = init + end-step events
__device__ unsigned g_cntA, g_genA, g_cntB, g_genB;

__device__ __forceinline__ float sigf(float x) { return 1.0f / (1.0f + expf(-x)); }

__device__ __forceinline__ uint32_t s2u(const void* p) {
    uint32_t a;
    asm("{ .reg .u64 t; cvta.to.shared.u64 t, %1; cvt.u32.u64 %0, t; }" : "=r"(a) : "l"(p));
    return a;
}
__device__ __forceinline__ uint2 pack_pair(float e0, float e1) {
    uint32_t hi, lo;
    asm("cvt.rn.bf16x2.f32 %0, %1, %2;" : "=r"(hi) : "f"(e1), "f"(e0));
    float r0 = e0 - __uint_as_float(hi << 16);
    float r1 = e1 - __uint_as_float(hi & 0xFFFF0000u);
    asm("cvt.rn.bf16x2.f32 %0, %1, %2;" : "=r"(lo) : "f"(r1), "f"(r0));
    return make_uint2(hi, lo);
}
__device__ __forceinline__ void bmma(float* c, uint32_t a0, uint32_t a1, uint32_t a2,
                                     uint32_t a3, uint32_t b0, uint32_t b1) {
    asm("mma.sync.aligned.m16n8k16.row.col.f32.bf16.bf16.f32 "
        "{%0,%1,%2,%3},{%4,%5,%6,%7},{%8,%9},{%0,%1,%2,%3};"
        : "+f"(c[0]), "+f"(c[1]), "+f"(c[2]), "+f"(c[3])
        : "r"(a0), "r"(a1), "r"(a2), "r"(a3), "r"(b0), "r"(b1));
}
__device__ __forceinline__ void mbar_init(uint32_t b, uint32_t n) {
    asm volatile("mbarrier.init.shared.b64 [%0], %1;" :: "r"(b), "r"(n) : "memory");
}
__device__ __forceinline__ void mexpect(uint32_t b, uint32_t tx) {
    asm volatile("mbarrier.arrive.expect_tx.shared.b64 _, [%0], %1;" :: "r"(b), "r"(tx) : "memory");
}
__device__ __forceinline__ void marrive(uint32_t b) {
    asm volatile("mbarrier.arrive.shared.b64 _, [%0];" :: "r"(b) : "memory");
}
__device__ __forceinline__ void mwait(uint32_t b, uint32_t ph) {
    asm volatile(
        "{\n\t.reg .pred P;\n"
        "W_%=:\n\t"
        "mbarrier.try_wait.parity.acquire.cta.shared::cta.b64 P, [%0], %1, 0x989680;\n\t"
        "@P bra D_%=;\n\t"
        "bra W_%=;\n"
        "D_%=:\n\t}"
        :: "r"(b), "r"(ph) : "memory");
}
__device__ __forceinline__ void bulk(uint32_t dst, const void* src, uint32_t bytes, uint32_t mbar) {
    asm volatile("cp.async.bulk.shared::cluster.global.mbarrier::complete_tx::bytes [%0], [%1], %2, [%3];"
        :: "r"(dst), "l"(src), "r"(bytes), "r"(mbar) : "memory");
}
__device__ __forceinline__ void barc() {   // compute-warps-only barrier (256 thr)
    asm volatile("bar.sync 1, 256;" ::: "memory");
}
__device__ __forceinline__ void arrive_evt(unsigned* cnt, unsigned* gen) {
    __threadfence();
    if (atomicAdd(cnt, 1u) == NCTA - 1) {
        *cnt = 0;
        __threadfence();
        atomicAdd(gen, 1u);
    }
}
__device__ __forceinline__ void wait_gen(volatile unsigned* gen, unsigned base, unsigned want) {
    while (*gen - base < want) { __nanosleep(64); }
    __threadfence();
}

// ---- prep: embeddings -> g_x (A-swizzled) ----
__global__ void prep_x(const int* __restrict__ ib, const float* __restrict__ emb) {
    const int N = TT * 128 * BB;
    for (int i = blockIdx.x * blockDim.x + threadIdx.x; i < N;
         i += gridDim.x * blockDim.x) {
        int m = i & 127;
        int p = (i >> 7) & 127;
        int t = i >> 14;
        const float* s = emb + (size_t)ib[m * TT + t] * 256 + 2 * p;
        g_x[t][p][m ^ ((p & 3) << 2)] = pack_pair(s[0], s[1]);
    }
}

// ---- prep: W -> packed [chunk][cb][p][c'] (B-swizzled) ----
__global__ void prep_w(const float* __restrict__ W0, const float* __restrict__ W1) {
    const long n0 = 20L * 131072, n1 = 32L * 131072;
    for (long i = (long)blockIdx.x * blockDim.x + threadIdx.x; i < n0 + n1;
         i += (long)gridDim.x * blockDim.x) {
        long j = i;
        const float* W = W0;
        uint2* dst = &g_w0[0][0][0][0];
        if (j >= n0) { j -= n0; W = W1; dst = &g_w1[0][0][0][0]; }
        int c  = (int)(j & 31);
        int p  = (int)((j >> 5) & 31);
        int cb = (int)((j >> 10) & 127);
        int ch = (int)(j >> 17);
        int gcol = ((c >> 3) & 3) * HH + cb * 8 + (c & 7);
        int k0 = 2 * (ch * 32 + p);
        dst[(j & ~31L) | (long)(c ^ ((p & 3) << 2))] =
            pack_pair(W[(size_t)k0 * 4096 + gcol],
                      W[(size_t)(k0 + 1) * 4096 + gcol]);
    }
}

__global__ void __launch_bounds__(NTHR, 1)
lstm_main(const int* __restrict__ il,
          const float* __restrict__ b0g,
          const float* __restrict__ b1g,
          float* __restrict__ out) {
    extern __shared__ char smem[];
    float* Zs  = (float*)(smem + ZS_OFF);
    float* sb0 = (float*)(smem + SB_OFF);
    float* sb1 = (float*)(smem + SB_OFF + 128);
    const uint32_t sbase = s2u(smem);

    const int tid = threadIdx.x;
    const int wid = tid >> 5, lid = tid & 31;
    const int cta = blockIdx.x;
    const int g = lid >> 2, q = lid & 3;
    const int mt = wid >> 1;          // m-tile of 32 rows (compute warps)
    const int kh = wid & 1;           // K-half of the chunk
    const int R = mt * 32;
    const int xr = q << 2;            // fragment swizzle

    const unsigned baseA = *(volatile unsigned*)&g_genA;
    const unsigned baseB = *(volatile unsigned*)&g_genB;

    if (tid == 0) {
        for (int s = 0; s < NSTG; s++) {
            mbar_init(sbase + FULL_MB(s), 1);
            mbar_init(sbase + EMPTY_MB(s), 8);
        }
    }
    if (tid < 32) {
        int gc = (tid >> 3) * HH + cta * 8 + (tid & 7);
        sb0[tid] = b0g[gc];
        sb1[tid] = b1g[gc];
    }
    {
        uint2 z2 = make_uint2(0u, 0u);
        uint2* z0 = &g_h0[0][0][0];
        uint2* z1 = &g_h1[0][0][0];
        for (int i = cta * NTHR + tid; i < 512 * BB; i += NCTA * NTHR) { z0[i] = z2; z1[i] = z2; }
    }
    __syncthreads();                       // last block-wide sync before role split

    // init barrier: event genB #1
    if (tid == 0) arrive_evt(&g_cntB, &g_genB);
    wait_gen(&g_genB, baseB, 1u);

    if (wid == 8) {
        // ================= dedicated free-running producer =================
        if (lid == 0) {
            int pstg = 0, pph = 1;
            for (int t = 0; t < TT; t++) {
                const int pr = t & 1, pw = pr ^ 1;
                // ---- layer 0: x chunks + h0[pr] (gated: mid(t-1), already waited) ----
                for (int c = 0; c < 20; c++) {
                    mwait(sbase + EMPTY_MB(pstg), (unsigned)pph);
                    mexpect(sbase + FULL_MB(pstg), 40960u);
                    const uint2* ap = (c < 4) ? &g_x[t][c * 32][0]
                                              : &g_h0[pr][c * 32 - 128][0];
                    bulk(sbase + pstg * 40960, ap, 32768u, sbase + FULL_MB(pstg));
                    bulk(sbase + pstg * 40960 + 32768, &g_w0[c][cta][0][0], 8192u,
                         sbase + FULL_MB(pstg));
                    if (++pstg == NSTG) { pstg = 0; pph ^= 1; }
                }
                // ---- layer 1 part A: h1[pr] chunks (gate: end(t-1) = genB >= t+1) ----
                wait_gen(&g_genB, baseB, (unsigned)(t + 1));
                for (int i = 0; i < 16; i++) {
                    const int c = 16 + i;
                    mwait(sbase + EMPTY_MB(pstg), (unsigned)pph);
                    mexpect(sbase + FULL_MB(pstg), 40960u);
                    bulk(sbase + pstg * 40960, &g_h1[pr][i * 32][0], 32768u,
                         sbase + FULL_MB(pstg));
                    bulk(sbase + pstg * 40960 + 32768, &g_w1[c][cta][0][0], 8192u,
                         sbase + FULL_MB(pstg));
                    if (++pstg == NSTG) { pstg = 0; pph ^= 1; }
                }
                // ---- layer 1 part B: h0[pw] chunks (gate: mid(t) = genA >= t+1) ----
                wait_gen(&g_genA, baseA, (unsigned)(t + 1));
                for (int c = 0; c < 16; c++) {
                    mwait(sbase + EMPTY_MB(pstg), (unsigned)pph);
                    mexpect(sbase + FULL_MB(pstg), 40960u);
                    bulk(sbase + pstg * 40960, &g_h0[pw][c * 32][0], 32768u,
                         sbase + FULL_MB(pstg));
                    bulk(sbase + pstg * 40960 + 32768, &g_w1[c][cta][0][0], 8192u,
                         sbase + FULL_MB(pstg));
                    if (++pstg == NSTG) { pstg = 0; pph ^= 1; }
                }
            }
        }
    } else {
        // ================= compute + cell (warps 0..7), never grid-blocked =================
        const int m  = tid >> 1;
        const int uh = (tid & 1) * 4;
        float cs0[4] = {0.f, 0.f, 0.f, 0.f};
        float cs1[4] = {0.f, 0.f, 0.f, 0.f};
        const int mylen = il[m];
        int cstg = 0, cph = 0;

        for (int t = 0; t < TT; t++) {
            const int pw = (t & 1) ^ 1;
            for (int layer = 0; layer < 2; layer++) {
                const int nc = layer ? 32 : 20;

                float C[2][4][4];
#pragma unroll
                for (int a = 0; a < 2; a++)
#pragma unroll
                    for (int b = 0; b < 4; b++)
#pragma unroll
                        for (int d = 0; d < 4; d++) C[a][b][d] = 0.f;

                for (int ch = 0; ch < nc; ch++) {
                    mwait(sbase + FULL_MB(cstg), (unsigned)cph);
                    const uint2* Ab = (const uint2*)(smem + cstg * 40960);
                    const uint2* Bb = (const uint2*)(smem + cstg * 40960 + 32768);

                    uint2 Af[2][2][4];
                    uint2 Bf[2][4][2];
#pragma unroll
                    for (int sl = 0; sl < 2; sl++) {
                        const int s  = kh * 2 + sl;
                        const int pa = (s * 8 + q) * 128;
                        const int pb = (s * 8 + q + 4) * 128;
#pragma unroll
                        for (int rt = 0; rt < 2; rt++) {
                            const int r0 = (R + rt * 16 + g) ^ xr;
                            const int r1 = (R + rt * 16 + g + 8) ^ xr;
                            Af[sl][rt][0] = Ab[pa + r0];
                            Af[sl][rt][1] = Ab[pa + r1];
                            Af[sl][rt][2] = Ab[pb + r0];
                            Af[sl][rt][3] = Ab[pb + r1];
                        }
                        const int ba  = (s * 8 + q) * 32;
                        const int bb2 = (s * 8 + q + 4) * 32;
#pragma unroll
                        for (int nt = 0; nt < 4; nt++) {
                            const int cc = (nt * 8 + g) ^ xr;
                            Bf[sl][nt][0] = Bb[ba + cc];
                            Bf[sl][nt][1] = Bb[bb2 + cc];
                        }
                    }
#pragma unroll
                    for (int sl = 0; sl < 2; sl++)
#pragma unroll
                        for (int rt = 0; rt < 2; rt++)
#pragma unroll
                            for (int nt = 0; nt < 4; nt++) {
                                bmma(C[rt][nt], Af[sl][rt][0].x, Af[sl][rt][1].x,
                                     Af[sl][rt][2].x, Af[sl][rt][3].x,
                                     Bf[sl][nt][0].x, Bf[sl][nt][1].x);
                                bmma(C[rt][nt], Af[sl][rt][0].y, Af[sl][rt][1].y,
                                     Af[sl][rt][2].y, Af[sl][rt][3].y,
                                     Bf[sl][nt][0].x, Bf[sl][nt][1].x);
                                bmma(C[rt][nt], Af[sl][rt][0].x, Af[sl][rt][1].x,
                                     Af[sl][rt][2].x, Af[sl][rt][3].x,
                                     Bf[sl][nt][0].y, Bf[sl][nt][1].y);
                            }
                    __syncwarp();
                    if (lid == 0) marrive(sbase + EMPTY_MB(cstg));
                    if (++cstg == NSTG) { cstg = 0; cph ^= 1; }
                }

                // epilogue: kh0 stores, then kh1 accumulates
                if (kh == 0) {
#pragma unroll
                    for (int rt = 0; rt < 2; rt++)
#pragma unroll
                        for (int nt = 0; nt < 4; nt++) {
                            const int col = nt * 8 + 2 * q;
                            *(float2*)&Zs[(R + rt * 16 + g) * 36 + col] =
                                make_float2(C[rt][nt][0], C[rt][nt][1]);
                            *(float2*)&Zs[(R + rt * 16 + g + 8) * 36 + col] =
                                make_float2(C[rt][nt][2], C[rt][nt][3]);
                        }
                }
                barc();
                if (kh == 1) {
#pragma unroll
                    for (int rt = 0; rt < 2; rt++)
#pragma unroll
                        for (int nt = 0; nt < 4; nt++) {
                            const int col = nt * 8 + 2 * q;
                            float2 v0 = *(float2*)&Zs[(R + rt * 16 + g) * 36 + col];
                            float2 v1 = *(float2*)&Zs[(R + rt * 16 + g + 8) * 36 + col];
                            v0.x += C[rt][nt][0]; v0.y += C[rt][nt][1];
                            v1.x += C[rt][nt][2]; v1.y += C[rt][nt][3];
                            *(float2*)&Zs[(R + rt * 16 + g) * 36 + col] = v0;
                            *(float2*)&Zs[(R + rt * 16 + g + 8) * 36 + col] = v1;
                        }
                }
                barc();

                // cell: threads 0..255, 4 units each
                {
                    const float* sb = layer ? sb1 : sb0;
                    float* cs = layer ? cs1 : cs0;
                    float4 vi = *(float4*)&Zs[m * 36 + 0 + uh];
                    float4 vj = *(float4*)&Zs[m * 36 + 8 + uh];
                    float4 vf = *(float4*)&Zs[m * 36 + 16 + uh];
                    float4 vo = *(float4*)&Zs[m * 36 + 24 + uh];
                    float ziv[4] = {vi.x, vi.y, vi.z, vi.w};
                    float zjv[4] = {vj.x, vj.y, vj.z, vj.w};
                    float zfv[4] = {vf.x, vf.y, vf.z, vf.w};
                    float zov[4] = {vo.x, vo.y, vo.z, vo.w};
                    float nh[4];
#pragma unroll
                    for (int j = 0; j < 4; j++) {
                        float zi = ziv[j] + sb[uh + j];
                        float zj = zjv[j] + sb[8 + uh + j];
                        float zf = zfv[j] + sb[16 + uh + j];
                        float zo = zov[j] + sb[24 + uh + j];
                        float nc = cs[j] * sigf(zf + 1.0f) + sigf(zi) * tanhf(zj);
                        nh[j] = tanhf(nc) * sigf(zo);
                        cs[j] = nc;
                    }
                    uint2 p0 = pack_pair(nh[0], nh[1]);
                    uint2 p1 = pack_pair(nh[2], nh[3]);
                    const int pg = cta * 4 + (tid & 1) * 2;
                    const int m0 = m ^ ((pg & 3) << 2);
                    const int m1 = m ^ (((pg + 1) & 3) << 2);
                    if (layer == 0) {
                        g_h0[pw][pg][m0] = p0;
                        g_h0[pw][pg + 1][m1] = p1;
                    } else {
                        g_h1[pw][pg][m0] = p0;
                        g_h1[pw][pg + 1][m1] = p1;
                        if (t == mylen - 1)
                            *(float4*)&out[m * HH + cta * 8 + uh] =
                                make_float4(nh[0], nh[1], nh[2], nh[3]);
                    }
                }
                barc();   // h writes done before tid0 arrives; also protects Zs reuse

                if (tid == 0) {
                    if (layer == 0) arrive_evt(&g_cntA, &g_genA);  // mid(t)
                    else            arrive_evt(&g_cntB, &g_genB);  // end(t)
                }
            }
        }
    }
}

extern "C" void kernel_launch(void* const* d_in, const int* in_sizes, int n_in,
                              void* d_out, int out_size) {
    const int*   input_batch   = (const int*)d_in[0];
    const int*   input_lengths = (const int*)d_in[1];
    const float* emb           = (const float*)d_in[2];
    const float* W0            = (const float*)d_in[3];
    const float* b0            = (const float*)d_in[4];
    const float* W1            = (const float*)d_in[5];
    const float* b1            = (const float*)d_in[6];
    float*       out           = (float*)d_out;

    cudaFuncSetAttribute(lstm_main, cudaFuncAttributeMaxDynamicSharedMemorySize, SMEM_DYN);
    prep_x<<<1024, 256>>>(input_batch, emb);
    prep_w<<<2048, 256>>>(W0, W1);
    lstm_main<<<NCTA, NTHR, SMEM_DYN>>>(input_lengths, b0, b1, out);
}

// round 12
// speedup vs baseline: 5.8927x; 1.1226x over previous
#include <cuda_runtime.h>
#include <math.h>
#include <stdint.h>

#define BB 128
#define TT 512
#define HH 1024
#define NCTA 128
#define NTHR 288
#define NSTG 5

// smem: stage s<5: A 32KB @ s*40960 ([mb4][p32][row32] uint2), B 8KB @ +32768
//       Zs float[128][36] @204800; sb @223232; mbars @223744
#define ZS_OFF   204800
#define SB_OFF   223232
#define MB_OFF   223744
#define FULL_MB(s)  (MB_OFF + (s) * 16)
#define EMPTY_MB(s) (MB_OFF + (s) * 16 + 8)
#define SMEM_DYN 223872

// ---- persistent device state: packed (bf16-hi, bf16-lo) pairs ----
// A images: [.. t/parity ..][m-block][pair][row32], row stored at (m&31)^((p&3)<<2)
// B images: [ch][cb][p][c], col stored at c^((p&3)<<2)
__device__ __align__(16) uint2 g_x [TT][4][128][32];
__device__ __align__(16) uint2 g_h0[2][4][512][32];
__device__ __align__(16) uint2 g_h1[2][4][512][32];
__device__ __align__(16) uint2 g_w0[20][128][32][32];
__device__ __align__(16) uint2 g_w1[32][128][32][32];
__device__ int g_perm[BB];   // sorted (desc length) -> original row
__device__ int g_plen[BB];   // sorted lengths
__device__ int g_nt[TT];     // alive rows at step t (= #{len > t}), non-increasing
// split grid-barrier counters: A = mid-step events, B = init + end-step events
__device__ unsigned g_cntA, g_genA, g_cntB, g_genB;

__device__ __forceinline__ float sigf(float x) { return 1.0f / (1.0f + expf(-x)); }

__device__ __forceinline__ uint32_t s2u(const void* p) {
    uint32_t a;
    asm("{ .reg .u64 t; cvta.to.shared.u64 t, %1; cvt.u32.u64 %0, t; }" : "=r"(a) : "l"(p));
    return a;
}
__device__ __forceinline__ uint2 pack_pair(float e0, float e1) {
    uint32_t hi, lo;
    asm("cvt.rn.bf16x2.f32 %0, %1, %2;" : "=r"(hi) : "f"(e1), "f"(e0));
    float r0 = e0 - __uint_as_float(hi << 16);
    float r1 = e1 - __uint_as_float(hi & 0xFFFF0000u);
    asm("cvt.rn.bf16x2.f32 %0, %1, %2;" : "=r"(lo) : "f"(r1), "f"(r0));
    return make_uint2(hi, lo);
}
__device__ __forceinline__ void bmma(float* c, uint32_t a0, uint32_t a1, uint32_t a2,
                                     uint32_t a3, uint32_t b0, uint32_t b1) {
    asm("mma.sync.aligned.m16n8k16.row.col.f32.bf16.bf16.f32 "
        "{%0,%1,%2,%3},{%4,%5,%6,%7},{%8,%9},{%0,%1,%2,%3};"
        : "+f"(c[0]), "+f"(c[1]), "+f"(c[2]), "+f"(c[3])
        : "r"(a0), "r"(a1), "r"(a2), "r"(a3), "r"(b0), "r"(b1));
}
__device__ __forceinline__ void mbar_init(uint32_t b, uint32_t n) {
    asm volatile("mbarrier.init.shared.b64 [%0], %1;" :: "r"(b), "r"(n) : "memory");
}
__device__ __forceinline__ void mexpect(uint32_t b, uint32_t tx) {
    asm volatile("mbarrier.arrive.expect_tx.shared.b64 _, [%0], %1;" :: "r"(b), "r"(tx) : "memory");
}
__device__ __forceinline__ void marrive(uint32_t b) {
    asm volatile("mbarrier.arrive.shared.b64 _, [%0];" :: "r"(b) : "memory");
}
__device__ __forceinline__ void mwait(uint32_t b, uint32_t ph) {
    asm volatile(
        "{\n\t.reg .pred P;\n"
        "W_%=:\n\t"
        "mbarrier.try_wait.parity.acquire.cta.shared::cta.b64 P, [%0], %1, 0x989680;\n\t"
        "@P bra D_%=;\n\t"
        "bra W_%=;\n"
        "D_%=:\n\t}"
        :: "r"(b), "r"(ph) : "memory");
}
__device__ __forceinline__ void bulk(uint32_t dst, const void* src, uint32_t bytes, uint32_t mbar) {
    asm volatile("cp.async.bulk.shared::cluster.global.mbarrier::complete_tx::bytes [%0], [%1], %2, [%3];"
        :: "r"(dst), "l"(src), "r"(bytes), "r"(mbar) : "memory");
}
__device__ __forceinline__ void barc() {   // compute-warps-only barrier (256 thr)
    asm volatile("bar.sync 1, 256;" ::: "memory");
}
__device__ __forceinline__ void arrive_evt(unsigned* cnt, unsigned* gen) {
    __threadfence();
    if (atomicAdd(cnt, 1u) == NCTA - 1) {
        *cnt = 0;
        __threadfence();
        atomicAdd(gen, 1u);
    }
}
__device__ __forceinline__ void wait_gen(volatile unsigned* gen, unsigned base, unsigned want) {
    while (*gen - base < want) { __nanosleep(64); }
    __threadfence();
}

// ---- prep: sort rows by length (desc), alive counts ----
__global__ void prep_perm(const int* __restrict__ il) {
    __shared__ int sl[BB];
    int i = threadIdx.x;
    sl[i] = il[i];
    __syncthreads();
    int L = sl[i], r = 0;
    for (int j = 0; j < BB; j++) {
        int Lj = sl[j];
        if (Lj > L || (Lj == L && j < i)) r++;
    }
    g_perm[r] = i;
    g_plen[r] = L;
    for (int k = 0; k < 4; k++) {
        int t = i * 4 + k;
        int c = 0;
        for (int j = 0; j < BB; j++) c += (sl[j] > t);
        g_nt[t] = c;
    }
}

// ---- prep: embeddings -> g_x (permuted rows, block layout, A-swizzled) ----
__global__ void prep_x(const int* __restrict__ ib, const float* __restrict__ emb) {
    const int N = TT * 128 * BB;
    for (int i = blockIdx.x * blockDim.x + threadIdx.x; i < N;
         i += gridDim.x * blockDim.x) {
        int m = i & 127;
        int p = (i >> 7) & 127;
        int t = i >> 14;
        const float* s = emb + (size_t)ib[g_perm[m] * TT + t] * 256 + 2 * p;
        g_x[t][m >> 5][p][(m & 31) ^ ((p & 3) << 2)] = pack_pair(s[0], s[1]);
    }
}

// ---- prep: W -> packed [chunk][cb][p][c'] (B-swizzled) ----
__global__ void prep_w(const float* __restrict__ W0, const float* __restrict__ W1) {
    const long n0 = 20L * 131072, n1 = 32L * 131072;
    for (long i = (long)blockIdx.x * blockDim.x + threadIdx.x; i < n0 + n1;
         i += (long)gridDim.x * blockDim.x) {
        long j = i;
        const float* W = W0;
        uint2* dst = &g_w0[0][0][0][0];
        if (j >= n0) { j -= n0; W = W1; dst = &g_w1[0][0][0][0]; }
        int c  = (int)(j & 31);
        int p  = (int)((j >> 5) & 31);
        int cb = (int)((j >> 10) & 127);
        int ch = (int)(j >> 17);
        int gcol = ((c >> 3) & 3) * HH + cb * 8 + (c & 7);
        int k0 = 2 * (ch * 32 + p);
        dst[(j & ~31L) | (long)(c ^ ((p & 3) << 2))] =
            pack_pair(W[(size_t)k0 * 4096 + gcol],
                      W[(size_t)(k0 + 1) * 4096 + gcol]);
    }
}

__global__ void __launch_bounds__(NTHR, 1)
lstm_main(const int* __restrict__ il,
          const float* __restrict__ b0g,
          const float* __restrict__ b1g,
          float* __restrict__ out) {
    extern __shared__ char smem[];
    float* Zs  = (float*)(smem + ZS_OFF);
    float* sb0 = (float*)(smem + SB_OFF);
    float* sb1 = (float*)(smem + SB_OFF + 128);
    const uint32_t sbase = s2u(smem);

    const int tid = threadIdx.x;
    const int wid = tid >> 5, lid = tid & 31;
    const int cta = blockIdx.x;
    const int g = lid >> 2, q = lid & 3;
    const int mt = wid >> 1;          // m-tile (32 rows) of compute warps
    const int kh = wid & 1;           // K-half of the chunk
    const int xr = q << 2;            // fragment swizzle

    const unsigned baseA = *(volatile unsigned*)&g_genA;
    const unsigned baseB = *(volatile unsigned*)&g_genB;

    if (tid == 0) {
        for (int s = 0; s < NSTG; s++) {
            mbar_init(sbase + FULL_MB(s), 1);
            mbar_init(sbase + EMPTY_MB(s), 8);
        }
    }
    if (tid < 32) {
        int gc = (tid >> 3) * HH + cta * 8 + (tid & 7);
        sb0[tid] = b0g[gc];
        sb1[tid] = b1g[gc];
    }
    {
        uint2 z2 = make_uint2(0u, 0u);
        uint2* z0 = &g_h0[0][0][0][0];
        uint2* z1 = &g_h1[0][0][0][0];
        for (int i = cta * NTHR + tid; i < 4 * 512 * 32; i += NCTA * NTHR) { z0[i] = z2; z1[i] = z2; }
    }
    __syncthreads();                       // last block-wide sync before role split

    // init barrier: event genB #1
    if (tid == 0) arrive_evt(&g_cntB, &g_genB);
    wait_gen(&g_genB, baseB, 1u);

    if (wid == 8) {
        // ================= dedicated free-running producer =================
        if (lid == 0) {
            int pstg = 0, pph = 1;
            for (int t = 0; t < TT; t++) {
                const int pr = t & 1, pw = pr ^ 1;
                const int nt  = __ldg(&g_nt[t]);
                if (nt == 0) continue;
                const int nmb = (nt + 31) >> 5;
                const uint32_t tx = (uint32_t)(nmb * 8192 + 8192);

                // ---- layer 0: x chunks + h0[pr] ----
                for (int c = 0; c < 20; c++) {
                    mwait(sbase + EMPTY_MB(pstg), (unsigned)pph);
                    mexpect(sbase + FULL_MB(pstg), tx);
                    for (int mb = 0; mb < nmb; mb++) {
                        const uint2* ap = (c < 4) ? &g_x[t][mb][c * 32][0]
                                                  : &g_h0[pr][mb][(c - 4) * 32][0];
                        bulk(sbase + pstg * 40960 + mb * 8192, ap, 8192u,
                             sbase + FULL_MB(pstg));
                    }
                    bulk(sbase + pstg * 40960 + 32768, &g_w0[c][cta][0][0], 8192u,
                         sbase + FULL_MB(pstg));
                    if (++pstg == NSTG) { pstg = 0; pph ^= 1; }
                }
                // ---- layer 1 part A: h1[pr] chunks (gate: end(t-1)) ----
                wait_gen(&g_genB, baseB, (unsigned)(t + 1));
                for (int i = 0; i < 16; i++) {
                    mwait(sbase + EMPTY_MB(pstg), (unsigned)pph);
                    mexpect(sbase + FULL_MB(pstg), tx);
                    for (int mb = 0; mb < nmb; mb++)
                        bulk(sbase + pstg * 40960 + mb * 8192, &g_h1[pr][mb][i * 32][0],
                             8192u, sbase + FULL_MB(pstg));
                    bulk(sbase + pstg * 40960 + 32768, &g_w1[16 + i][cta][0][0], 8192u,
                         sbase + FULL_MB(pstg));
                    if (++pstg == NSTG) { pstg = 0; pph ^= 1; }
                }
                // ---- layer 1 part B: h0[pw] chunks (gate: mid(t)) ----
                wait_gen(&g_genA, baseA, (unsigned)(t + 1));
                for (int c = 0; c < 16; c++) {
                    mwait(sbase + EMPTY_MB(pstg), (unsigned)pph);
                    mexpect(sbase + FULL_MB(pstg), tx);
                    for (int mb = 0; mb < nmb; mb++)
                        bulk(sbase + pstg * 40960 + mb * 8192, &g_h0[pw][mb][c * 32][0],
                             8192u, sbase + FULL_MB(pstg));
                    bulk(sbase + pstg * 40960 + 32768, &g_w1[c][cta][0][0], 8192u,
                         sbase + FULL_MB(pstg));
                    if (++pstg == NSTG) { pstg = 0; pph ^= 1; }
                }
            }
        }
    } else {
        // ================= compute + cell (warps 0..7) =================
        const int m  = tid >> 1;
        const int uh = (tid & 1) * 4;
        float cs0[4] = {0.f, 0.f, 0.f, 0.f};
        float cs1[4] = {0.f, 0.f, 0.f, 0.f};
        const int om    = g_perm[m];
        const int mylen = g_plen[m];
        int cstg = 0, cph = 0;

        for (int t = 0; t < TT; t++) {
            const int pw = (t & 1) ^ 1;
            const int nt = __ldg(&g_nt[t]);
            for (int layer = 0; layer < 2; layer++) {
                if (nt == 0) {
                    if (tid == 0) {
                        if (layer == 0) arrive_evt(&g_cntA, &g_genA);
                        else            arrive_evt(&g_cntB, &g_genB);
                    }
                    continue;
                }
                const int nc = layer ? 32 : 20;
                const int nmb = (nt + 31) >> 5;
                const bool live = (mt < nmb);

                float C[2][4][4];
#pragma unroll
                for (int a = 0; a < 2; a++)
#pragma unroll
                    for (int b = 0; b < 4; b++)
#pragma unroll
                        for (int d = 0; d < 4; d++) C[a][b][d] = 0.f;

                for (int ch = 0; ch < nc; ch++) {
                    mwait(sbase + FULL_MB(cstg), (unsigned)cph);
                    if (live) {
                        const uint2* Ab = (const uint2*)(smem + cstg * 40960) + mt * 1024;
                        const uint2* Bb = (const uint2*)(smem + cstg * 40960 + 32768);
                        uint2 Af[2][2][4];
                        uint2 Bf[2][4][2];
#pragma unroll
                        for (int sl = 0; sl < 2; sl++) {
                            const int s  = kh * 2 + sl;
                            const int pa = (s * 8 + q) * 32;
                            const int pb = (s * 8 + q + 4) * 32;
#pragma unroll
                            for (int rt = 0; rt < 2; rt++) {
                                const int v0 = (rt * 16 + g) ^ xr;
                                const int v1 = (rt * 16 + g + 8) ^ xr;
                                Af[sl][rt][0] = Ab[pa + v0];
                                Af[sl][rt][1] = Ab[pa + v1];
                                Af[sl][rt][2] = Ab[pb + v0];
                                Af[sl][rt][3] = Ab[pb + v1];
                            }
                            const int ba  = (s * 8 + q) * 32;
                            const int bb2 = (s * 8 + q + 4) * 32;
#pragma unroll
                            for (int nt2 = 0; nt2 < 4; nt2++) {
                                const int cc = (nt2 * 8 + g) ^ xr;
                                Bf[sl][nt2][0] = Bb[ba + cc];
                                Bf[sl][nt2][1] = Bb[bb2 + cc];
                            }
                        }
#pragma unroll
                        for (int sl = 0; sl < 2; sl++)
#pragma unroll
                            for (int rt = 0; rt < 2; rt++)
#pragma unroll
                                for (int nt2 = 0; nt2 < 4; nt2++) {
                                    bmma(C[rt][nt2], Af[sl][rt][0].x, Af[sl][rt][1].x,
                                         Af[sl][rt][2].x, Af[sl][rt][3].x,
                                         Bf[sl][nt2][0].x, Bf[sl][nt2][1].x);
                                    bmma(C[rt][nt2], Af[sl][rt][0].y, Af[sl][rt][1].y,
                                         Af[sl][rt][2].y, Af[sl][rt][3].y,
                                         Bf[sl][nt2][0].x, Bf[sl][nt2][1].x);
                                    bmma(C[rt][nt2], Af[sl][rt][0].x, Af[sl][rt][1].x,
                                         Af[sl][rt][2].x, Af[sl][rt][3].x,
                                         Bf[sl][nt2][0].y, Bf[sl][nt2][1].y);
                                }
                    }
                    __syncwarp();
                    if (lid == 0) marrive(sbase + EMPTY_MB(cstg));
                    if (++cstg == NSTG) { cstg = 0; cph ^= 1; }
                }

                const int R = mt * 32;
                if (live && kh == 0) {
#pragma unroll
                    for (int rt = 0; rt < 2; rt++)
#pragma unroll
                        for (int nt2 = 0; nt2 < 4; nt2++) {
                            const int col = nt2 * 8 + 2 * q;
                            *(float2*)&Zs[(R + rt * 16 + g) * 36 + col] =
                                make_float2(C[rt][nt2][0], C[rt][nt2][1]);
                            *(float2*)&Zs[(R + rt * 16 + g + 8) * 36 + col] =
                                make_float2(C[rt][nt2][2], C[rt][nt2][3]);
                        }
                }
                barc();
                if (live && kh == 1) {
#pragma unroll
                    for (int rt = 0; rt < 2; rt++)
#pragma unroll
                        for (int nt2 = 0; nt2 < 4; nt2++) {
                            const int col = nt2 * 8 + 2 * q;
                            float2 v0 = *(float2*)&Zs[(R + rt * 16 + g) * 36 + col];
                            float2 v1 = *(float2*)&Zs[(R + rt * 16 + g + 8) * 36 + col];
                            v0.x += C[rt][nt2][0]; v0.y += C[rt][nt2][1];
                            v1.x += C[rt][nt2][2]; v1.y += C[rt][nt2][3];
                            *(float2*)&Zs[(R + rt * 16 + g) * 36 + col] = v0;
                            *(float2*)&Zs[(R + rt * 16 + g + 8) * 36 + col] = v1;
                        }
                }
                barc();

                // cell: alive rows only
                if (m < nt) {
                    const float* sb = layer ? sb1 : sb0;
                    float* cs = layer ? cs1 : cs0;
                    float4 vi = *(float4*)&Zs[m * 36 + 0 + uh];
                    float4 vj = *(float4*)&Zs[m * 36 + 8 + uh];
                    float4 vf = *(float4*)&Zs[m * 36 + 16 + uh];
                    float4 vo = *(float4*)&Zs[m * 36 + 24 + uh];
                    float ziv[4] = {vi.x, vi.y, vi.z, vi.w};
                    float zjv[4] = {vj.x, vj.y, vj.z, vj.w};
                    float zfv[4] = {vf.x, vf.y, vf.z, vf.w};
                    float zov[4] = {vo.x, vo.y, vo.z, vo.w};
                    float nh[4];
#pragma unroll
                    for (int j = 0; j < 4; j++) {
                        float zi = ziv[j] + sb[uh + j];
                        float zj = zjv[j] + sb[8 + uh + j];
                        float zf = zfv[j] + sb[16 + uh + j];
                        float zo = zov[j] + sb[24 + uh + j];
                        float nc = cs[j] * sigf(zf + 1.0f) + sigf(zi) * tanhf(zj);
                        nh[j] = tanhf(nc) * sigf(zo);
                        cs[j] = nc;
                    }
                    uint2 p0 = pack_pair(nh[0], nh[1]);
                    uint2 p1 = pack_pair(nh[2], nh[3]);
                    const int pg = cta * 4 + (tid & 1) * 2;
                    const int mb = m >> 5;
                    const int m0 = (m & 31) ^ ((pg & 3) << 2);
                    const int m1 = (m & 31) ^ (((pg + 1) & 3) << 2);
                    if (layer == 0) {
                        g_h0[pw][mb][pg][m0] = p0;
                        g_h0[pw][mb][pg + 1][m1] = p1;
                    } else {
                        g_h1[pw][mb][pg][m0] = p0;
                        g_h1[pw][mb][pg + 1][m1] = p1;
                        if (t == mylen - 1)
                            *(float4*)&out[om * HH + cta * 8 + uh] =
                                make_float4(nh[0], nh[1], nh[2], nh[3]);
                    }
                }
                barc();   // h writes done before tid0 arrives; also protects Zs reuse

                if (tid == 0) {
                    if (layer == 0) arrive_evt(&g_cntA, &g_genA);  // mid(t)
                    else            arrive_evt(&g_cntB, &g_genB);  // end(t)
                }
            }
        }
    }
}

extern "C" void kernel_launch(void* const* d_in, const int* in_sizes, int n_in,
                              void* d_out, int out_size) {
    const int*   input_batch   = (const int*)d_in[0];
    const int*   input_lengths = (const int*)d_in[1];
    const float* emb           = (const float*)d_in[2];
    const float* W0            = (const float*)d_in[3];
    const float* b0            = (const float*)d_in[4];
    const float* W1            = (const float*)d_in[5];
    const float* b1            = (const float*)d_in[6];
    float*       out           = (float*)d_out;

    cudaFuncSetAttribute(lstm_main, cudaFuncAttributeMaxDynamicSharedMemorySize, SMEM_DYN);
    prep_perm<<<1, 128>>>(input_lengths);
    prep_x<<<1024, 256>>>(input_batch, emb);
    prep_w<<<2048, 256>>>(W0, W1);
    lstm_main<<<NCTA, NTHR, SMEM_DYN>>>(input_lengths, b0, b1, out);
}

// round 13
// speedup vs baseline: 5.9806x; 1.0149x over previous
#include <cuda_runtime.h>
#include <math.h>
#include <stdint.h>

#define BB 128
#define TT 512
#define HH 1024
#define NCTA 128
#define NTHR 544
#define NSTG 4

// smem: stage s<4: A 32KB @ s*40960 ([mb4][p32][row32] uint2), B 8KB @ +32768
//       ZsA @163840, ZsB @182272 (each float[128][36]); sb @200704; mbars @201216
#define ZSA_OFF  163840
#define ZSB_OFF  182272
#define SB_OFF   200704
#define MB_OFF   201216
#define FULL_MB(s)  (MB_OFF + (s) * 16)
#define EMPTY_MB(s) (MB_OFF + (s) * 16 + 8)
#define SMEM_DYN 201344

// ---- persistent device state: packed (bf16-hi, bf16-lo) pairs ----
// A images: [t/parity][m-block][pair][row32], row stored at (m&31)^((p&3)<<2)
// B images: [ch][cb][p][c], col stored at c^((p&3)<<2)
__device__ __align__(16) uint2 g_x [TT][4][128][32];
__device__ __align__(16) uint2 g_h0[2][4][512][32];
__device__ __align__(16) uint2 g_h1[2][4][512][32];
__device__ __align__(16) uint2 g_w0[20][128][32][32];
__device__ __align__(16) uint2 g_w1[32][128][32][32];
__device__ int g_perm[BB];
__device__ int g_plen[BB];
__device__ int g_nt[TT];
__device__ unsigned g_cntA, g_genA, g_cntB, g_genB;

__device__ __forceinline__ float sigf(float x) { return 1.0f / (1.0f + expf(-x)); }

__device__ __forceinline__ uint32_t s2u(const void* p) {
    uint32_t a;
    asm("{ .reg .u64 t; cvta.to.shared.u64 t, %1; cvt.u32.u64 %0, t; }" : "=r"(a) : "l"(p));
    return a;
}
__device__ __forceinline__ uint2 pack_pair(float e0, float e1) {
    uint32_t hi, lo;
    asm("cvt.rn.bf16x2.f32 %0, %1, %2;" : "=r"(hi) : "f"(e1), "f"(e0));
    float r0 = e0 - __uint_as_float(hi << 16);
    float r1 = e1 - __uint_as_float(hi & 0xFFFF0000u);
    asm("cvt.rn.bf16x2.f32 %0, %1, %2;" : "=r"(lo) : "f"(r1), "f"(r0));
    return make_uint2(hi, lo);
}
__device__ __forceinline__ void bmma(float* c, uint32_t a0, uint32_t a1, uint32_t a2,
                                     uint32_t a3, uint32_t b0, uint32_t b1) {
    asm("mma.sync.aligned.m16n8k16.row.col.f32.bf16.bf16.f32 "
        "{%0,%1,%2,%3},{%4,%5,%6,%7},{%8,%9},{%0,%1,%2,%3};"
        : "+f"(c[0]), "+f"(c[1]), "+f"(c[2]), "+f"(c[3])
        : "r"(a0), "r"(a1), "r"(a2), "r"(a3), "r"(b0), "r"(b1));
}
__device__ __forceinline__ void mbar_init(uint32_t b, uint32_t n) {
    asm volatile("mbarrier.init.shared.b64 [%0], %1;" :: "r"(b), "r"(n) : "memory");
}
__device__ __forceinline__ void mexpect(uint32_t b, uint32_t tx) {
    asm volatile("mbarrier.arrive.expect_tx.shared.b64 _, [%0], %1;" :: "r"(b), "r"(tx) : "memory");
}
__device__ __forceinline__ void marrive(uint32_t b) {
    asm volatile("mbarrier.arrive.shared.b64 _, [%0];" :: "r"(b) : "memory");
}
__device__ __forceinline__ void mwait(uint32_t b, uint32_t ph) {
    asm volatile(
        "{\n\t.reg .pred P;\n"
        "W_%=:\n\t"
        "mbarrier.try_wait.parity.acquire.cta.shared::cta.b64 P, [%0], %1, 0x989680;\n\t"
        "@P bra D_%=;\n\t"
        "bra W_%=;\n"
        "D_%=:\n\t}"
        :: "r"(b), "r"(ph) : "memory");
}
__device__ __forceinline__ void bulk(uint32_t dst, const void* src, uint32_t bytes, uint32_t mbar) {
    asm volatile("cp.async.bulk.shared::cluster.global.mbarrier::complete_tx::bytes [%0], [%1], %2, [%3];"
        :: "r"(dst), "l"(src), "r"(bytes), "r"(mbar) : "memory");
}
__device__ __forceinline__ void barc() {   // compute-warps barrier (512 thr)
    asm volatile("bar.sync 1, 512;" ::: "memory");
}
__device__ __forceinline__ void arrive_evt(unsigned* cnt, unsigned* gen) {
    __threadfence();
    if (atomicAdd(cnt, 1u) == NCTA - 1) {
        *cnt = 0;
        __threadfence();
        atomicAdd(gen, 1u);
    }
}
__device__ __forceinline__ void wait_gen(volatile unsigned* gen, unsigned base, unsigned want) {
    while (*gen - base < want) { __nanosleep(64); }
    __threadfence();
}

// ---- prep: sort rows by length (desc), alive counts ----
__global__ void prep_perm(const int* __restrict__ il) {
    __shared__ int sl[BB];
    int i = threadIdx.x;
    sl[i] = il[i];
    __syncthreads();
    int L = sl[i], r = 0;
    for (int j = 0; j < BB; j++) {
        int Lj = sl[j];
        if (Lj > L || (Lj == L && j < i)) r++;
    }
    g_perm[r] = i;
    g_plen[r] = L;
    for (int k = 0; k < 4; k++) {
        int t = i * 4 + k;
        int c = 0;
        for (int j = 0; j < BB; j++) c += (sl[j] > t);
        g_nt[t] = c;
    }
}

// ---- prep: embeddings -> g_x (permuted rows, block layout, A-swizzled) ----
__global__ void prep_x(const int* __restrict__ ib, const float* __restrict__ emb) {
    const int N = TT * 128 * BB;
    for (int i = blockIdx.x * blockDim.x + threadIdx.x; i < N;
         i += gridDim.x * blockDim.x) {
        int m = i & 127;
        int p = (i >> 7) & 127;
        int t = i >> 14;
        const float* s = emb + (size_t)ib[g_perm[m] * TT + t] * 256 + 2 * p;
        g_x[t][m >> 5][p][(m & 31) ^ ((p & 3) << 2)] = pack_pair(s[0], s[1]);
    }
}

// ---- prep: W -> packed [chunk][cb][p][c'] (B-swizzled) ----
__global__ void prep_w(const float* __restrict__ W0, const float* __restrict__ W1) {
    const long n0 = 20L * 131072, n1 = 32L * 131072;
    for (long i = (long)blockIdx.x * blockDim.x + threadIdx.x; i < n0 + n1;
         i += (long)gridDim.x * blockDim.x) {
        long j = i;
        const float* W = W0;
        uint2* dst = &g_w0[0][0][0][0];
        if (j >= n0) { j -= n0; W = W1; dst = &g_w1[0][0][0][0]; }
        int c  = (int)(j & 31);
        int p  = (int)((j >> 5) & 31);
        int cb = (int)((j >> 10) & 127);
        int ch = (int)(j >> 17);
        int gcol = ((c >> 3) & 3) * HH + cb * 8 + (c & 7);
        int k0 = 2 * (ch * 32 + p);
        dst[(j & ~31L) | (long)(c ^ ((p & 3) << 2))] =
            pack_pair(W[(size_t)k0 * 4096 + gcol],
                      W[(size_t)(k0 + 1) * 4096 + gcol]);
    }
}

__global__ void __launch_bounds__(NTHR, 1)
lstm_main(const int* __restrict__ il,
          const float* __restrict__ b0g,
          const float* __restrict__ b1g,
          float* __restrict__ out) {
    extern __shared__ char smem[];
    float* ZsA = (float*)(smem + ZSA_OFF);
    float* ZsB = (float*)(smem + ZSB_OFF);
    float* sb0 = (float*)(smem + SB_OFF);
    float* sb1 = (float*)(smem + SB_OFF + 128);
    const uint32_t sbase = s2u(smem);

    const int tid = threadIdx.x;
    const int wid = tid >> 5, lid = tid & 31;
    const int cta = blockIdx.x;
    const int g = lid >> 2, q = lid & 3;
    const int mt = wid >> 2;          // m-tile (32 rows), compute warps
    const int kq = wid & 3;           // K-quarter of the chunk
    const int xr = q << 2;            // fragment swizzle

    const unsigned baseA = *(volatile unsigned*)&g_genA;
    const unsigned baseB = *(volatile unsigned*)&g_genB;

    if (tid == 0) {
        for (int s = 0; s < NSTG; s++) {
            mbar_init(sbase + FULL_MB(s), 1);
            mbar_init(sbase + EMPTY_MB(s), 16);
        }
    }
    if (tid < 32) {
        int gc = (tid >> 3) * HH + cta * 8 + (tid & 7);
        sb0[tid] = b0g[gc];
        sb1[tid] = b1g[gc];
    }
    {
        uint2 z2 = make_uint2(0u, 0u);
        uint2* z0 = &g_h0[0][0][0][0];
        uint2* z1 = &g_h1[0][0][0][0];
        for (int i = cta * NTHR + tid; i < 4 * 512 * 32; i += NCTA * NTHR) { z0[i] = z2; z1[i] = z2; }
    }
    __syncthreads();                       // last block-wide sync before role split

    if (tid == 0) arrive_evt(&g_cntB, &g_genB);
    wait_gen(&g_genB, baseB, 1u);

    if (wid == 16) {
        // ================= dedicated free-running producer =================
        if (lid == 0) {
            int pstg = 0, pph = 1;
            for (int t = 0; t < TT; t++) {
                const int pr = t & 1, pw = pr ^ 1;
                const int nt  = __ldg(&g_nt[t]);
                if (nt == 0) continue;
                const int nmb = (nt + 31) >> 5;
                const uint32_t tx = (uint32_t)(nmb * 8192 + 8192);

                for (int c = 0; c < 20; c++) {
                    mwait(sbase + EMPTY_MB(pstg), (unsigned)pph);
                    mexpect(sbase + FULL_MB(pstg), tx);
                    for (int mb = 0; mb < nmb; mb++) {
                        const uint2* ap = (c < 4) ? &g_x[t][mb][c * 32][0]
                                                  : &g_h0[pr][mb][(c - 4) * 32][0];
                        bulk(sbase + pstg * 40960 + mb * 8192, ap, 8192u,
                             sbase + FULL_MB(pstg));
                    }
                    bulk(sbase + pstg * 40960 + 32768, &g_w0[c][cta][0][0], 8192u,
                         sbase + FULL_MB(pstg));
                    if (++pstg == NSTG) { pstg = 0; pph ^= 1; }
                }
                wait_gen(&g_genB, baseB, (unsigned)(t + 1));
                for (int i = 0; i < 16; i++) {
                    mwait(sbase + EMPTY_MB(pstg), (unsigned)pph);
                    mexpect(sbase + FULL_MB(pstg), tx);
                    for (int mb = 0; mb < nmb; mb++)
                        bulk(sbase + pstg * 40960 + mb * 8192, &g_h1[pr][mb][i * 32][0],
                             8192u, sbase + FULL_MB(pstg));
                    bulk(sbase + pstg * 40960 + 32768, &g_w1[16 + i][cta][0][0], 8192u,
                         sbase + FULL_MB(pstg));
                    if (++pstg == NSTG) { pstg = 0; pph ^= 1; }
                }
                wait_gen(&g_genA, baseA, (unsigned)(t + 1));
                for (int c = 0; c < 16; c++) {
                    mwait(sbase + EMPTY_MB(pstg), (unsigned)pph);
                    mexpect(sbase + FULL_MB(pstg), tx);
                    for (int mb = 0; mb < nmb; mb++)
                        bulk(sbase + pstg * 40960 + mb * 8192, &g_h0[pw][mb][c * 32][0],
                             8192u, sbase + FULL_MB(pstg));
                    bulk(sbase + pstg * 40960 + 32768, &g_w1[c][cta][0][0], 8192u,
                         sbase + FULL_MB(pstg));
                    if (++pstg == NSTG) { pstg = 0; pph ^= 1; }
                }
            }
        }
    } else {
        // ================= compute + cell (warps 0..15) =================
        const int m  = tid >> 1;          // valid for tid < 256
        const int uh = (tid & 1) * 4;
        float cs0[4] = {0.f, 0.f, 0.f, 0.f};
        float cs1[4] = {0.f, 0.f, 0.f, 0.f};
        const int om    = (tid < 256) ? g_perm[m] : 0;
        const int mylen = (tid < 256) ? g_plen[m] : 0;
        int cstg = 0, cph = 0;

        for (int t = 0; t < TT; t++) {
            const int pw = (t & 1) ^ 1;
            const int nt = __ldg(&g_nt[t]);
            for (int layer = 0; layer < 2; layer++) {
                if (nt == 0) {
                    if (tid == 0) {
                        if (layer == 0) arrive_evt(&g_cntA, &g_genA);
                        else            arrive_evt(&g_cntB, &g_genB);
                    }
                    continue;
                }
                const int nc = layer ? 32 : 20;
                const int nmb = (nt + 31) >> 5;
                const bool live = (mt < nmb);

                float C[2][4][4];
#pragma unroll
                for (int a = 0; a < 2; a++)
#pragma unroll
                    for (int b = 0; b < 4; b++)
#pragma unroll
                        for (int d = 0; d < 4; d++) C[a][b][d] = 0.f;

                for (int ch = 0; ch < nc; ch++) {
                    mwait(sbase + FULL_MB(cstg), (unsigned)cph);
                    if (live) {
                        const uint2* Ab = (const uint2*)(smem + cstg * 40960) + mt * 1024;
                        const uint2* Bb = (const uint2*)(smem + cstg * 40960 + 32768);
                        uint2 Af[2][4];
                        uint2 Bf[4][2];
                        const int pa = (kq * 8 + q) * 32;
                        const int pb = (kq * 8 + q + 4) * 32;
#pragma unroll
                        for (int rt = 0; rt < 2; rt++) {
                            const int v0 = (rt * 16 + g) ^ xr;
                            const int v1 = (rt * 16 + g + 8) ^ xr;
                            Af[rt][0] = Ab[pa + v0];
                            Af[rt][1] = Ab[pa + v1];
                            Af[rt][2] = Ab[pb + v0];
                            Af[rt][3] = Ab[pb + v1];
                        }
#pragma unroll
                        for (int nt2 = 0; nt2 < 4; nt2++) {
                            const int cc = (nt2 * 8 + g) ^ xr;
                            Bf[nt2][0] = Bb[pa + cc];
                            Bf[nt2][1] = Bb[pb + cc];
                        }
#pragma unroll
                        for (int rt = 0; rt < 2; rt++)
#pragma unroll
                            for (int nt2 = 0; nt2 < 4; nt2++) {
                                bmma(C[rt][nt2], Af[rt][0].x, Af[rt][1].x,
                                     Af[rt][2].x, Af[rt][3].x,
                                     Bf[nt2][0].x, Bf[nt2][1].x);
                                bmma(C[rt][nt2], Af[rt][0].y, Af[rt][1].y,
                                     Af[rt][2].y, Af[rt][3].y,
                                     Bf[nt2][0].x, Bf[nt2][1].x);
                                bmma(C[rt][nt2], Af[rt][0].x, Af[rt][1].x,
                                     Af[rt][2].x, Af[rt][3].x,
                                     Bf[nt2][0].y, Bf[nt2][1].y);
                            }
                    }
                    __syncwarp();
                    if (lid == 0) marrive(sbase + EMPTY_MB(cstg));
                    if (++cstg == NSTG) { cstg = 0; cph ^= 1; }
                }

                // staged 4-way reduction: kq0->ZsA, kq2->ZsB; then kq1 +=A, kq3 +=B
                const int R = mt * 32;
                float* Zdst = (kq & 2) ? ZsB : ZsA;
                if (live && (kq == 0 || kq == 2)) {
#pragma unroll
                    for (int rt = 0; rt < 2; rt++)
#pragma unroll
                        for (int nt2 = 0; nt2 < 4; nt2++) {
                            const int col = nt2 * 8 + 2 * q;
                            *(float2*)&Zdst[(R + rt * 16 + g) * 36 + col] =
                                make_float2(C[rt][nt2][0], C[rt][nt2][1]);
                            *(float2*)&Zdst[(R + rt * 16 + g + 8) * 36 + col] =
                                make_float2(C[rt][nt2][2], C[rt][nt2][3]);
                        }
                }
                barc();
                if (live && (kq == 1 || kq == 3)) {
#pragma unroll
                    for (int rt = 0; rt < 2; rt++)
#pragma unroll
                        for (int nt2 = 0; nt2 < 4; nt2++) {
                            const int col = nt2 * 8 + 2 * q;
                            float2 v0 = *(float2*)&Zdst[(R + rt * 16 + g) * 36 + col];
                            float2 v1 = *(float2*)&Zdst[(R + rt * 16 + g + 8) * 36 + col];
                            v0.x += C[rt][nt2][0]; v0.y += C[rt][nt2][1];
                            v1.x += C[rt][nt2][2]; v1.y += C[rt][nt2][3];
                            *(float2*)&Zdst[(R + rt * 16 + g) * 36 + col] = v0;
                            *(float2*)&Zdst[(R + rt * 16 + g + 8) * 36 + col] = v1;
                        }
                }
                barc();

                // cell: alive rows only (threads 0..255)
                if (tid < 256 && m < nt) {
                    const float* sb = layer ? sb1 : sb0;
                    float* cs = layer ? cs1 : cs0;
                    float4 ai = *(float4*)&ZsA[m * 36 + 0 + uh];
                    float4 aj = *(float4*)&ZsA[m * 36 + 8 + uh];
                    float4 af = *(float4*)&ZsA[m * 36 + 16 + uh];
                    float4 ao = *(float4*)&ZsA[m * 36 + 24 + uh];
                    float4 bi = *(float4*)&ZsB[m * 36 + 0 + uh];
                    float4 bj = *(float4*)&ZsB[m * 36 + 8 + uh];
                    float4 bf = *(float4*)&ZsB[m * 36 + 16 + uh];
                    float4 bo = *(float4*)&ZsB[m * 36 + 24 + uh];
                    float ziv[4] = {ai.x + bi.x, ai.y + bi.y, ai.z + bi.z, ai.w + bi.w};
                    float zjv[4] = {aj.x + bj.x, aj.y + bj.y, aj.z + bj.z, aj.w + bj.w};
                    float zfv[4] = {af.x + bf.x, af.y + bf.y, af.z + bf.z, af.w + bf.w};
                    float zov[4] = {ao.x + bo.x, ao.y + bo.y, ao.z + bo.z, ao.w + bo.w};
                    float nh[4];
#pragma unroll
                    for (int j = 0; j < 4; j++) {
                        float zi = ziv[j] + sb[uh + j];
                        float zj = zjv[j] + sb[8 + uh + j];
                        float zf = zfv[j] + sb[16 + uh + j];
                        float zo = zov[j] + sb[24 + uh + j];
                        float nc = cs[j] * sigf(zf + 1.0f) + sigf(zi) * tanhf(zj);
                        nh[j] = tanhf(nc) * sigf(zo);
                        cs[j] = nc;
                    }
                    uint2 p0 = pack_pair(nh[0], nh[1]);
                    uint2 p1 = pack_pair(nh[2], nh[3]);
                    const int pg = cta * 4 + (tid & 1) * 2;
                    const int mb = m >> 5;
                    const int m0 = (m & 31) ^ ((pg & 3) << 2);
                    const int m1 = (m & 31) ^ (((pg + 1) & 3) << 2);
                    if (layer == 0) {
                        g_h0[pw][mb][pg][m0] = p0;
                        g_h0[pw][mb][pg + 1][m1] = p1;
                    } else {
                        g_h1[pw][mb][pg][m0] = p0;
                        g_h1[pw][mb][pg + 1][m1] = p1;
                        if (t == mylen - 1)
                            *(float4*)&out[om * HH + cta * 8 + uh] =
                                make_float4(nh[0], nh[1], nh[2], nh[3]);
                    }
                }
                barc();   // h writes done before tid0 arrives; also protects Zs reuse

                if (tid == 0) {
                    if (layer == 0) arrive_evt(&g_cntA, &g_genA);  // mid(t)
                    else            arrive_evt(&g_cntB, &g_genB);  // end(t)
                }
            }
        }
    }
}

extern "C" void kernel_launch(void* const* d_in, const int* in_sizes, int n_in,
                              void* d_out, int out_size) {
    const int*   input_batch   = (const int*)d_in[0];
    const int*   input_lengths = (const int*)d_in[1];
    const float* emb           = (const float*)d_in[2];
    const float* W0            = (const float*)d_in[3];
    const float* b0            = (const float*)d_in[4];
    const float* W1            = (const float*)d_in[5];
    const float* b1            = (const float*)d_in[6];
    float*       out           = (float*)d_out;

    cudaFuncSetAttribute(lstm_main, cudaFuncAttributeMaxDynamicSharedMemorySize, SMEM_DYN);
    prep_perm<<<1, 128>>>(input_lengths);
    prep_x<<<1024, 256>>>(input_batch, emb);
    prep_w<<<2048, 256>>>(W0, W1);
    lstm_main<<<NCTA, NTHR, SMEM_DYN>>>(input_lengths, b0, b1, out);
}

// round 14
// speedup vs baseline: 6.3831x; 1.0673x over previous
#include <cuda_runtime.h>
#include <math.h>
#include <stdint.h>

#define BB 128
#define TT 512
#define HH 1024
#define NCTA 128
#define NTHR 544
#define NSTG 4

// smem: stage s<4: A 32KB @ s*40960 ([mb4][p32][row32] uint2), B 8KB @ +32768
//       ZsA @163840, ZsB @182272 (each float[128][36]); sb @200704; mbars @201216
#define ZSA_OFF  163840
#define ZSB_OFF  182272
#define SB_OFF   200704
#define MB_OFF   201216
#define EMPTY_MB(s)  (MB_OFF + (s) * 48)
#define B_MB(s)      (MB_OFF + (s) * 48 + 8)
#define A_MB(s, mb)  (MB_OFF + (s) * 48 + 16 + (mb) * 8)
#define SMEM_DYN 201472

// ---- persistent device state: packed (bf16-hi, bf16-lo) pairs ----
// A images: [t/parity][m-block][pair][row32], row stored at (m&31)^((p&3)<<2)
// B images: [ch][cb][p][c], col stored at c^((p&3)<<2)
__device__ __align__(16) uint2 g_x [TT][4][128][32];
__device__ __align__(16) uint2 g_h0[2][4][512][32];
__device__ __align__(16) uint2 g_h1[2][4][512][32];
__device__ __align__(16) uint2 g_w0[20][128][32][32];
__device__ __align__(16) uint2 g_w1[32][128][32][32];
__device__ int g_perm[BB];
__device__ int g_plen[BB];
__device__ int g_nt[TT];
__device__ unsigned g_cntA, g_genA, g_cntB, g_genB;

__device__ __forceinline__ float sigf(float x) {
    return __fdividef(1.0f, 1.0f + __expf(-x));
}
__device__ __forceinline__ float tanf_fast(float x) {
    float cx = fminf(fmaxf(x, -15.0f), 15.0f);
    float e = __expf(2.0f * cx);
    return (e - 1.0f) * __fdividef(1.0f, e + 1.0f);
}

__device__ __forceinline__ uint32_t s2u(const void* p) {
    uint32_t a;
    asm("{ .reg .u64 t; cvta.to.shared.u64 t, %1; cvt.u32.u64 %0, t; }" : "=r"(a) : "l"(p));
    return a;
}
__device__ __forceinline__ uint2 pack_pair(float e0, float e1) {
    uint32_t hi, lo;
    asm("cvt.rn.bf16x2.f32 %0, %1, %2;" : "=r"(hi) : "f"(e1), "f"(e0));
    float r0 = e0 - __uint_as_float(hi << 16);
    float r1 = e1 - __uint_as_float(hi & 0xFFFF0000u);
    asm("cvt.rn.bf16x2.f32 %0, %1, %2;" : "=r"(lo) : "f"(r1), "f"(r0));
    return make_uint2(hi, lo);
}
__device__ __forceinline__ void bmma(float* c, uint32_t a0, uint32_t a1, uint32_t a2,
                                     uint32_t a3, uint32_t b0, uint32_t b1) {
    asm("mma.sync.aligned.m16n8k16.row.col.f32.bf16.bf16.f32 "
        "{%0,%1,%2,%3},{%4,%5,%6,%7},{%8,%9},{%0,%1,%2,%3};"
        : "+f"(c[0]), "+f"(c[1]), "+f"(c[2]), "+f"(c[3])
        : "r"(a0), "r"(a1), "r"(a2), "r"(a3), "r"(b0), "r"(b1));
}
__device__ __forceinline__ void mbar_init(uint32_t b, uint32_t n) {
    asm volatile("mbarrier.init.shared.b64 [%0], %1;" :: "r"(b), "r"(n) : "memory");
}
__device__ __forceinline__ void mexpect(uint32_t b, uint32_t tx) {
    asm volatile("mbarrier.arrive.expect_tx.shared.b64 _, [%0], %1;" :: "r"(b), "r"(tx) : "memory");
}
__device__ __forceinline__ void marrive(uint32_t b) {
    asm volatile("mbarrier.arrive.shared.b64 _, [%0];" :: "r"(b) : "memory");
}
__device__ __forceinline__ void mwait(uint32_t b, uint32_t ph) {
    asm volatile(
        "{\n\t.reg .pred P;\n"
        "W_%=:\n\t"
        "mbarrier.try_wait.parity.acquire.cta.shared::cta.b64 P, [%0], %1, 0x989680;\n\t"
        "@P bra D_%=;\n\t"
        "bra W_%=;\n"
        "D_%=:\n\t}"
        :: "r"(b), "r"(ph) : "memory");
}
__device__ __forceinline__ void bulk(uint32_t dst, const void* src, uint32_t bytes, uint32_t mbar) {
    asm volatile("cp.async.bulk.shared::cluster.global.mbarrier::complete_tx::bytes [%0], [%1], %2, [%3];"
        :: "r"(dst), "l"(src), "r"(bytes), "r"(mbar) : "memory");
}
__device__ __forceinline__ void barc() {   // compute-warps barrier (512 thr)
    asm volatile("bar.sync 1, 512;" ::: "memory");
}
__device__ __forceinline__ void arrive_evt(unsigned* cnt, unsigned* gen) {
    __threadfence();
    if (atomicAdd(cnt, 1u) == NCTA - 1) {
        *cnt = 0;
        __threadfence();
        atomicAdd(gen, 1u);
    }
}
__device__ __forceinline__ void wait_gen(volatile unsigned* gen, unsigned base, unsigned want) {
    while (*gen - base < want) { __nanosleep(64); }
    __threadfence();
}

// ---- prep: sort rows by length (desc), alive counts ----
__global__ void prep_perm(const int* __restrict__ il) {
    __shared__ int sl[BB];
    int i = threadIdx.x;
    sl[i] = il[i];
    __syncthreads();
    int L = sl[i], r = 0;
    for (int j = 0; j < BB; j++) {
        int Lj = sl[j];
        if (Lj > L || (Lj == L && j < i)) r++;
    }
    g_perm[r] = i;
    g_plen[r] = L;
    for (int k = 0; k < 4; k++) {
        int t = i * 4 + k;
        int c = 0;
        for (int j = 0; j < BB; j++) c += (sl[j] > t);
        g_nt[t] = c;
    }
}

// ---- prep: embeddings -> g_x (permuted rows, block layout, A-swizzled) ----
__global__ void prep_x(const int* __restrict__ ib, const float* __restrict__ emb) {
    const int N = TT * 128 * BB;
    for (int i = blockIdx.x * blockDim.x + threadIdx.x; i < N;
         i += gridDim.x * blockDim.x) {
        int m = i & 127;
        int p = (i >> 7) & 127;
        int t = i >> 14;
        const float* s = emb + (size_t)ib[g_perm[m] * TT + t] * 256 + 2 * p;
        g_x[t][m >> 5][p][(m & 31) ^ ((p & 3) << 2)] = pack_pair(s[0], s[1]);
    }
}

// ---- prep: W -> packed [chunk][cb][p][c'] (B-swizzled) ----
__global__ void prep_w(const float* __restrict__ W0, const float* __restrict__ W1) {
    const long n0 = 20L * 131072, n1 = 32L * 131072;
    for (long i = (long)blockIdx.x * blockDim.x + threadIdx.x; i < n0 + n1;
         i += (long)gridDim.x * blockDim.x) {
        long j = i;
        const float* W = W0;
        uint2* dst = &g_w0[0][0][0][0];
        if (j >= n0) { j -= n0; W = W1; dst = &g_w1[0][0][0][0]; }
        int c  = (int)(j & 31);
        int p  = (int)((j >> 5) & 31);
        int cb = (int)((j >> 10) & 127);
        int ch = (int)(j >> 17);
        int gcol = ((c >> 3) & 3) * HH + cb * 8 + (c & 7);
        int k0 = 2 * (ch * 32 + p);
        dst[(j & ~31L) | (long)(c ^ ((p & 3) << 2))] =
            pack_pair(W[(size_t)k0 * 4096 + gcol],
                      W[(size_t)(k0 + 1) * 4096 + gcol]);
    }
}

__global__ void __launch_bounds__(NTHR, 1)
lstm_main(const int* __restrict__ il,
          const float* __restrict__ b0g,
          const float* __restrict__ b1g,
          float* __restrict__ out) {
    extern __shared__ char smem[];
    float* ZsA = (float*)(smem + ZSA_OFF);
    float* ZsB = (float*)(smem + ZSB_OFF);
    float* sb0 = (float*)(smem + SB_OFF);
    float* sb1 = (float*)(smem + SB_OFF + 128);
    const uint32_t sbase = s2u(smem);

    const int tid = threadIdx.x;
    const int wid = tid >> 5, lid = tid & 31;
    const int cta = blockIdx.x;
    const int g = lid >> 2, q = lid & 3;
    const int mt = wid >> 2;          // m-tile (32 rows), compute warps
    const int kq = wid & 3;           // K-quarter of the chunk
    const int xr = q << 2;            // fragment swizzle

    const unsigned baseA = *(volatile unsigned*)&g_genA;
    const unsigned baseB = *(volatile unsigned*)&g_genB;

    if (tid == 0) {
        for (int s = 0; s < NSTG; s++) {
            mbar_init(sbase + EMPTY_MB(s), 16);
            mbar_init(sbase + B_MB(s), 1);
            for (int mb = 0; mb < 4; mb++) mbar_init(sbase + A_MB(s, mb), 1);
        }
    }
    if (tid < 32) {
        int gc = (tid >> 3) * HH + cta * 8 + (tid & 7);
        sb0[tid] = b0g[gc];
        sb1[tid] = b1g[gc];
    }
    {
        uint2 z2 = make_uint2(0u, 0u);
        uint2* z0 = &g_h0[0][0][0][0];
        uint2* z1 = &g_h1[0][0][0][0];
        for (int i = cta * NTHR + tid; i < 4 * 512 * 32; i += NCTA * NTHR) { z0[i] = z2; z1[i] = z2; }
    }
    __syncthreads();                       // last block-wide sync before role split

    if (tid == 0) arrive_evt(&g_cntB, &g_genB);
    wait_gen(&g_genB, baseB, 1u);

    if (wid == 16) {
        // ============ dedicated free-running producer (lanes 0..4) ============
        if (lid < 8) {
            int pstg = 0, pph = 1;
            for (int t = 0; t < TT; t++) {
                const int pr = t & 1, pw = pr ^ 1;
                const int nt  = __ldg(&g_nt[t]);
                if (nt == 0) continue;
                const int nmb = (nt + 31) >> 5;

                // ---- layer 0: x + h0[pr] ----
                for (int c = 0; c < 20; c++) {
                    mwait(sbase + EMPTY_MB(pstg), (unsigned)pph);
                    if (lid < nmb) {
                        const uint2* ap = (c < 4) ? &g_x[t][lid][c * 32][0]
                                                  : &g_h0[pr][lid][(c - 4) * 32][0];
                        mexpect(sbase + A_MB(pstg, lid), 8192u);
                        bulk(sbase + pstg * 40960 + lid * 8192, ap, 8192u,
                             sbase + A_MB(pstg, lid));
                    }
                    if (lid == 4) {
                        mexpect(sbase + B_MB(pstg), 8192u);
                        bulk(sbase + pstg * 40960 + 32768, &g_w0[c][cta][0][0], 8192u,
                             sbase + B_MB(pstg));
                    }
                    if (++pstg == NSTG) { pstg = 0; pph ^= 1; }
                }
                // ---- layer 1 part A: h1[pr] (gate: end(t-1)) ----
                wait_gen(&g_genB, baseB, (unsigned)(t + 1));
                for (int i = 0; i < 16; i++) {
                    mwait(sbase + EMPTY_MB(pstg), (unsigned)pph);
                    if (lid < nmb) {
                        mexpect(sbase + A_MB(pstg, lid), 8192u);
                        bulk(sbase + pstg * 40960 + lid * 8192, &g_h1[pr][lid][i * 32][0],
                             8192u, sbase + A_MB(pstg, lid));
                    }
                    if (lid == 4) {
                        mexpect(sbase + B_MB(pstg), 8192u);
                        bulk(sbase + pstg * 40960 + 32768, &g_w1[16 + i][cta][0][0], 8192u,
                             sbase + B_MB(pstg));
                    }
                    if (++pstg == NSTG) { pstg = 0; pph ^= 1; }
                }
                // ---- layer 1 part B: h0[pw] (gate: mid(t)) ----
                wait_gen(&g_genA, baseA, (unsigned)(t + 1));
                for (int c = 0; c < 16; c++) {
                    mwait(sbase + EMPTY_MB(pstg), (unsigned)pph);
                    if (lid < nmb) {
                        mexpect(sbase + A_MB(pstg, lid), 8192u);
                        bulk(sbase + pstg * 40960 + lid * 8192, &g_h0[pw][lid][c * 32][0],
                             8192u, sbase + A_MB(pstg, lid));
                    }
                    if (lid == 4) {
                        mexpect(sbase + B_MB(pstg), 8192u);
                        bulk(sbase + pstg * 40960 + 32768, &g_w1[c][cta][0][0], 8192u,
                             sbase + B_MB(pstg));
                    }
                    if (++pstg == NSTG) { pstg = 0; pph ^= 1; }
                }
            }
        }
    } else {
        // ================= compute + cell (warps 0..15) =================
        const int m  = tid >> 1;          // valid for tid < 256
        const int uh = (tid & 1) * 4;
        float cs0[4] = {0.f, 0.f, 0.f, 0.f};
        float cs1[4] = {0.f, 0.f, 0.f, 0.f};
        const int om    = (tid < 256) ? g_perm[m] : 0;
        const int mylen = (tid < 256) ? g_plen[m] : 0;
        int cstg = 0, cph = 0;

        for (int t = 0; t < TT; t++) {
            const int pw = (t & 1) ^ 1;
            const int nt = __ldg(&g_nt[t]);
            for (int layer = 0; layer < 2; layer++) {
                if (nt == 0) {
                    if (tid == 0) {
                        if (layer == 0) arrive_evt(&g_cntA, &g_genA);
                        else            arrive_evt(&g_cntB, &g_genB);
                    }
                    continue;
                }
                const int nc = layer ? 32 : 20;
                const int nmb = (nt + 31) >> 5;
                const bool live = (mt < nmb);

                float C[2][4][4];
#pragma unroll
                for (int a = 0; a < 2; a++)
#pragma unroll
                    for (int b = 0; b < 4; b++)
#pragma unroll
                        for (int d = 0; d < 4; d++) C[a][b][d] = 0.f;

                for (int ch = 0; ch < nc; ch++) {
                    // wait only what this warp consumes
                    mwait(sbase + B_MB(cstg), (unsigned)cph);
                    if (live) {
                        mwait(sbase + A_MB(cstg, mt), (unsigned)cph);
                        const uint2* Ab = (const uint2*)(smem + cstg * 40960) + mt * 1024;
                        const uint2* Bb = (const uint2*)(smem + cstg * 40960 + 32768);
                        uint2 Af[2][4];
                        uint2 Bf[4][2];
                        const int pa = (kq * 8 + q) * 32;
                        const int pb = (kq * 8 + q + 4) * 32;
#pragma unroll
                        for (int rt = 0; rt < 2; rt++) {
                            const int v0 = (rt * 16 + g) ^ xr;
                            const int v1 = (rt * 16 + g + 8) ^ xr;
                            Af[rt][0] = Ab[pa + v0];
                            Af[rt][1] = Ab[pa + v1];
                            Af[rt][2] = Ab[pb + v0];
                            Af[rt][3] = Ab[pb + v1];
                        }
#pragma unroll
                        for (int nt2 = 0; nt2 < 4; nt2++) {
                            const int cc = (nt2 * 8 + g) ^ xr;
                            Bf[nt2][0] = Bb[pa + cc];
                            Bf[nt2][1] = Bb[pb + cc];
                        }
#pragma unroll
                        for (int rt = 0; rt < 2; rt++)
#pragma unroll
                            for (int nt2 = 0; nt2 < 4; nt2++) {
                                bmma(C[rt][nt2], Af[rt][0].x, Af[rt][1].x,
                                     Af[rt][2].x, Af[rt][3].x,
                                     Bf[nt2][0].x, Bf[nt2][1].x);
                                bmma(C[rt][nt2], Af[rt][0].y, Af[rt][1].y,
                                     Af[rt][2].y, Af[rt][3].y,
                                     Bf[nt2][0].x, Bf[nt2][1].x);
                                bmma(C[rt][nt2], Af[rt][0].x, Af[rt][1].x,
                                     Af[rt][2].x, Af[rt][3].x,
                                     Bf[nt2][0].y, Bf[nt2][1].y);
                            }
                    }
                    __syncwarp();
                    if (lid == 0) marrive(sbase + EMPTY_MB(cstg));
                    if (++cstg == NSTG) { cstg = 0; cph ^= 1; }
                }

                // staged 4-way reduction: kq0->ZsA, kq2->ZsB; then kq1 +=A, kq3 +=B
                const int R = mt * 32;
                float* Zdst = (kq & 2) ? ZsB : ZsA;
                if (live && (kq == 0 || kq == 2)) {
#pragma unroll
                    for (int rt = 0; rt < 2; rt++)
#pragma unroll
                        for (int nt2 = 0; nt2 < 4; nt2++) {
                            const int col = nt2 * 8 + 2 * q;
                            *(float2*)&Zdst[(R + rt * 16 + g) * 36 + col] =
                                make_float2(C[rt][nt2][0], C[rt][nt2][1]);
                            *(float2*)&Zdst[(R + rt * 16 + g + 8) * 36 + col] =
                                make_float2(C[rt][nt2][2], C[rt][nt2][3]);
                        }
                }
                barc();
                if (live && (kq == 1 || kq == 3)) {
#pragma unroll
                    for (int rt = 0; rt < 2; rt++)
#pragma unroll
                        for (int nt2 = 0; nt2 < 4; nt2++) {
                            const int col = nt2 * 8 + 2 * q;
                            float2 v0 = *(float2*)&Zdst[(R + rt * 16 + g) * 36 + col];
                            float2 v1 = *(float2*)&Zdst[(R + rt * 16 + g + 8) * 36 + col];
                            v0.x += C[rt][nt2][0]; v0.y += C[rt][nt2][1];
                            v1.x += C[rt][nt2][2]; v1.y += C[rt][nt2][3];
                            *(float2*)&Zdst[(R + rt * 16 + g) * 36 + col] = v0;
                            *(float2*)&Zdst[(R + rt * 16 + g + 8) * 36 + col] = v1;
                        }
                }
                barc();

                // cell: alive rows only (threads 0..255)
                if (tid < 256 && m < nt) {
                    const float* sb = layer ? sb1 : sb0;
                    float* cs = layer ? cs1 : cs0;
                    float4 ai = *(float4*)&ZsA[m * 36 + 0 + uh];
                    float4 aj = *(float4*)&ZsA[m * 36 + 8 + uh];
                    float4 af = *(float4*)&ZsA[m * 36 + 16 + uh];
                    float4 ao = *(float4*)&ZsA[m * 36 + 24 + uh];
                    float4 bi = *(float4*)&ZsB[m * 36 + 0 + uh];
                    float4 bj = *(float4*)&ZsB[m * 36 + 8 + uh];
                    float4 bf = *(float4*)&ZsB[m * 36 + 16 + uh];
                    float4 bo = *(float4*)&ZsB[m * 36 + 24 + uh];
                    float ziv[4] = {ai.x + bi.x, ai.y + bi.y, ai.z + bi.z, ai.w + bi.w};
                    float zjv[4] = {aj.x + bj.x, aj.y + bj.y, aj.z + bj.z, aj.w + bj.w};
                    float zfv[4] = {af.x + bf.x, af.y + bf.y, af.z + bf.z, af.w + bf.w};
                    float zov[4] = {ao.x + bo.x, ao.y + bo.y, ao.z + bo.z, ao.w + bo.w};
                    float nh[4];
#pragma unroll
                    for (int j = 0; j < 4; j++) {
                        float zi = ziv[j] + sb[uh + j];
                        float zj = zjv[j] + sb[8 + uh + j];
                        float zf = zfv[j] + sb[16 + uh + j];
                        float zo = zov[j] + sb[24 + uh + j];
                        float nc = cs[j] * sigf(zf + 1.0f) + sigf(zi) * tanf_fast(zj);
                        nh[j] = tanf_fast(nc) * sigf(zo);
                        cs[j] = nc;
                    }
                    uint2 p0 = pack_pair(nh[0], nh[1]);
                    uint2 p1 = pack_pair(nh[2], nh[3]);
                    const int pg = cta * 4 + (tid & 1) * 2;
                    const int mb = m >> 5;
                    const int m0 = (m & 31) ^ ((pg & 3) << 2);
                    const int m1 = (m & 31) ^ (((pg + 1) & 3) << 2);
                    if (layer == 0) {
                        g_h0[pw][mb][pg][m0] = p0;
                        g_h0[pw][mb][pg + 1][m1] = p1;
                    } else {
                        g_h1[pw][mb][pg][m0] = p0;
                        g_h1[pw][mb][pg + 1][m1] = p1;
                        if (t == mylen - 1)
                            *(float4*)&out[om * HH + cta * 8 + uh] =
                                make_float4(nh[0], nh[1], nh[2], nh[3]);
                    }
                }
                barc();   // h writes done before tid0 arrives; also protects Zs reuse

                if (tid == 0) {
                    if (layer == 0) arrive_evt(&g_cntA, &g_genA);  // mid(t)
                    else            arrive_evt(&g_cntB, &g_genB);  // end(t)
                }
            }
        }
    }
}

extern "C" void kernel_launch(void* const* d_in, const int* in_sizes, int n_in,
                              void* d_out, int out_size) {
    const int*   input_batch   = (const int*)d_in[0];
    const int*   input_lengths = (const int*)d_in[1];
    const float* emb           = (const float*)d_in[2];
    const float* W0            = (const float*)d_in[3];
    const float* b0            = (const float*)d_in[4];
    const float* W1            = (const float*)d_in[5];
    const float* b1            = (const float*)d_in[6];
    float*       out           = (float*)d_out;

    cudaFuncSetAttribute(lstm_main, cudaFuncAttributeMaxDynamicSharedMemorySize, SMEM_DYN);
    prep_perm<<<1, 128>>>(input_lengths);
    prep_x<<<1024, 256>>>(input_batch, emb);
    prep_w<<<2048, 256>>>(W0, W1);
    lstm_main<<<NCTA, NTHR, SMEM_DYN>>>(input_lengths, b0, b1, out);
}